// round 3
// baseline (speedup 1.0000x reference)
#include <cuda_runtime.h>
#include <cuda_bf16.h>
#include <cstdint>

// Fused: h = x @ W + b ; h = gamma*(h-mean)*rsqrt(var+eps)+beta ; out = sparsemax(h)
// B=65536, D=512, F=512 (D,F hardcoded; B derived from in_sizes).
//
// One block computes BM=32 full output rows (all 512 cols) so sparsemax runs
// in-register with warp shuffles. 8 warps, 4 rows/warp, 16 cols/lane.
// K-loop is double-buffered (BK=8, 2 buffers, one __syncthreads per tile).
// Sparsemax tau via bisection on g(tau)=sum(max(0,z-tau))-1 (monotone),
// tau in [zmax-1, zmax], 30 iterations -> |tau err| ~ 1e-9 << 1e-3 gate.

#define BM 32
#define BK 8
#define FDIM 512
#define THREADS 256
#define BN_EPS 1e-5f

__global__ __launch_bounds__(THREADS, 2)
void fused_dense_bn_sparsemax(const float* __restrict__ x,
                              const float* __restrict__ W,
                              const float* __restrict__ bias,
                              const float* __restrict__ gamma,
                              const float* __restrict__ beta,
                              const float* __restrict__ mmean,
                              const float* __restrict__ mvar,
                              float* __restrict__ out)
{
    __shared__ float As[2][BK][BM];      // transposed A tile: [buf][k][row]  (2 KB)
    __shared__ float Bs[2][BK][FDIM];    // B tile: [buf][k][f]               (32 KB)

    const int tid  = threadIdx.x;
    const int warp = tid >> 5;
    const int lane = tid & 31;
    const int r0   = blockIdx.x * BM;

    float acc[4][16];
    #pragma unroll
    for (int i = 0; i < 4; i++)
        #pragma unroll
        for (int j = 0; j < 16; j++)
            acc[i][j] = 0.0f;

    // A-tile loader params: 64 threads, each one float4 (4 consecutive k of one row)
    const int a_row = tid >> 1;          // 0..31 (valid when tid < 64)
    const int a_q   = (tid & 1) * 4;     // 0 or 4

    // ---- prologue: load tile 0 into buffer 0
    {
        if (tid < 64) {
            float4 v = *reinterpret_cast<const float4*>(
                &x[(size_t)(r0 + a_row) * FDIM + a_q]);
            As[0][a_q + 0][a_row] = v.x;
            As[0][a_q + 1][a_row] = v.y;
            As[0][a_q + 2][a_row] = v.z;
            As[0][a_q + 3][a_row] = v.w;
        }
        #pragma unroll
        for (int t = 0; t < 4; t++) {
            int idx = tid + t * 256;     // float4 index 0..1023
            int kk  = idx >> 7;          // 128 float4 per 512-float row
            int f4  = idx & 127;
            *reinterpret_cast<float4*>(&Bs[0][kk][f4 * 4]) =
                *reinterpret_cast<const float4*>(&W[(size_t)kk * FDIM + f4 * 4]);
        }
    }
    __syncthreads();

    const int NK = FDIM / BK;            // 64 tiles
    for (int t = 0; t < NK; t++) {
        const int cur = t & 1;
        const int nxt = cur ^ 1;
        const int k1  = (t + 1) * BK;

        // ---- prefetch next tile into the other buffer (overlaps with compute)
        if (t + 1 < NK) {
            if (tid < 64) {
                float4 v = *reinterpret_cast<const float4*>(
                    &x[(size_t)(r0 + a_row) * FDIM + k1 + a_q]);
                As[nxt][a_q + 0][a_row] = v.x;
                As[nxt][a_q + 1][a_row] = v.y;
                As[nxt][a_q + 2][a_row] = v.z;
                As[nxt][a_q + 3][a_row] = v.w;
            }
            #pragma unroll
            for (int tt = 0; tt < 4; tt++) {
                int idx = tid + tt * 256;
                int kk  = idx >> 7;
                int f4  = idx & 127;
                *reinterpret_cast<float4*>(&Bs[nxt][kk][f4 * 4]) =
                    *reinterpret_cast<const float4*>(&W[(size_t)(k1 + kk) * FDIM + f4 * 4]);
            }
        }

        // ---- compute current tile
        #pragma unroll
        for (int kk = 0; kk < BK; kk++) {
            float a[4];
            #pragma unroll
            for (int i = 0; i < 4; i++) a[i] = As[cur][kk][warp * 4 + i];
            #pragma unroll
            for (int j = 0; j < 16; j++) {
                float bv = Bs[cur][kk][lane + 32 * j];
                #pragma unroll
                for (int i = 0; i < 4; i++)
                    acc[i][j] = fmaf(a[i], bv, acc[i][j]);
            }
        }
        __syncthreads();
    }

    // ---- epilogue: per-column affine (bias + BN folded)
    // h = (acc + b)*s + (beta - mean*s)  where s = gamma*rsqrt(var+eps)
    float scl[16], shf[16];
    #pragma unroll
    for (int j = 0; j < 16; j++) {
        int f = lane + 32 * j;
        float s = gamma[f] * rsqrtf(mvar[f] + BN_EPS);
        scl[j] = s;
        shf[j] = fmaf(bias[f] - mmean[f], s, beta[f]);
    }
    #pragma unroll
    for (int i = 0; i < 4; i++)
        #pragma unroll
        for (int j = 0; j < 16; j++)
            acc[i][j] = fmaf(acc[i][j], scl[j], shf[j]);

    // ---- sparsemax per row (row's 512 values live in this warp: 16/lane)
    #pragma unroll
    for (int i = 0; i < 4; i++) {
        // row max
        float m = -1e30f;
        #pragma unroll
        for (int j = 0; j < 16; j++) m = fmaxf(m, acc[i][j]);
        #pragma unroll
        for (int off = 16; off > 0; off >>= 1)
            m = fmaxf(m, __shfl_xor_sync(0xFFFFFFFFu, m, off));

        // bisection: sum(max(0, z - tau)) = 1, tau in [m-1, m]
        float lo = m - 1.0f, hi = m;
        #pragma unroll 1
        for (int it = 0; it < 30; it++) {
            float tau = 0.5f * (lo + hi);
            float s = 0.0f;
            #pragma unroll
            for (int j = 0; j < 16; j++) s += fmaxf(acc[i][j] - tau, 0.0f);
            #pragma unroll
            for (int off = 16; off > 0; off >>= 1)
                s += __shfl_xor_sync(0xFFFFFFFFu, s, off);
            if (s >= 1.0f) lo = tau; else hi = tau;
        }
        float tau = 0.5f * (lo + hi);

        const int row = r0 + warp * 4 + i;
        float* orow = &out[(size_t)row * FDIM];
        #pragma unroll
        for (int j = 0; j < 16; j++)
            orow[lane + 32 * j] = fmaxf(acc[i][j] - tau, 0.0f);
    }
}

extern "C" void kernel_launch(void* const* d_in, const int* in_sizes, int n_in,
                              void* d_out, int out_size)
{
    const float* x     = (const float*)d_in[0];
    const float* W     = (const float*)d_in[1];
    const float* b     = (const float*)d_in[2];
    const float* gamma = (const float*)d_in[3];
    const float* beta  = (const float*)d_in[4];
    const float* mmean = (const float*)d_in[5];
    const float* mvar  = (const float*)d_in[6];
    float* out = (float*)d_out;

    int B = in_sizes[0] / FDIM;          // 65536
    int grid = B / BM;                   // 2048
    fused_dense_bn_sparsemax<<<grid, THREADS>>>(x, W, b, gamma, beta, mmean, mvar, out);
}

// round 6
// speedup vs baseline: 2.1194x; 2.1194x over previous
#include <cuda_runtime.h>
#include <cuda_bf16.h>
#include <cstdint>

// Fused sparsemax(BN(x @ W + b)) via warp-level mma.sync (bf16 hi/lo split, 3
// passes, fp32 accum). tcgen05 is unavailable (harness PTX target is plain
// compute_100); mma.sync/ldmatrix are sm_80 features and run on the tensor
// pipe as HMMA.
//
// prep kernel: g_WT[kc][n][kk] = bf16split(s_n * W[k][n]),  s_n = gamma*rsqrt(var+eps)
// main kernel: BM=64 rows/CTA, 8 warps, warp tile 64 rows x 64 cols
// (Mt=4, Nt=8), K-step 16, double-buffered SMEM, cp.async for W tiles,
// XOR-swizzled 16B chunks so every ldmatrix.x4 phase is conflict-free.
// Epilogue: accums -> padded SMEM stage -> row-per-warp bisection sparsemax.

#define FDIM 512
#define BM 64
#define THREADS 256
#define KSTEPS 32
#define BN_EPS 1e-5f
#define STG_STRIDE 520                  // 512 + 8 pad (floats)

// ---- device scratch (no allocation) ----
__device__ __align__(128) __nv_bfloat16 g_WT_hi[FDIM * FDIM];  // [kc][n][kk]
__device__ __align__(128) __nv_bfloat16 g_WT_lo[FDIM * FDIM];

// ---- smem layout (bytes) ----
#define A_HI_OFF(b) ((b) * 2048)                 // [0, 4096)
#define A_LO_OFF(b) (4096 + (b) * 2048)          // [4096, 8192)
#define B_HI_OFF(b) (8192 + (b) * 16384)         // [8192, 40960)
#define B_LO_OFF(b) (40960 + (b) * 16384)        // [40960, 73728)
#define SMEM_BYTES (BM * STG_STRIDE * 4)         // 133120 (stage unions over tiles)

// 16B-chunk offset inside a [rows][16 bf16] tile, XOR-swizzled so that 8
// consecutive rows (one ldmatrix phase) hit 8 distinct 16B slots of a 128B line.
#define TOFF(r, kc) (((((r) << 1) | (kc)) ^ (((r) >> 2) & 1)) << 4)

__device__ __forceinline__ uint32_t smem_u32(const void* p) {
    uint32_t a;
    asm("{ .reg .u64 t; cvta.to.shared.u64 t, %1; cvt.u32.u64 %0, t; }" : "=r"(a) : "l"(p));
    return a;
}

#define LDSM4(R, addr)                                                        \
    asm volatile("ldmatrix.sync.aligned.m8n8.x4.shared.b16 {%0,%1,%2,%3}, [%4];" \
                 : "=r"((R)[0]), "=r"((R)[1]), "=r"((R)[2]), "=r"((R)[3])     \
                 : "r"(addr))

#define MMA16816(d, a, b0, b1)                                                \
    asm volatile("mma.sync.aligned.m16n8k16.row.col.f32.bf16.bf16.f32 "       \
                 "{%0,%1,%2,%3},{%4,%5,%6,%7},{%8,%9},{%0,%1,%2,%3};"         \
                 : "+f"((d)[0]), "+f"((d)[1]), "+f"((d)[2]), "+f"((d)[3])     \
                 : "r"((a)[0]), "r"((a)[1]), "r"((a)[2]), "r"((a)[3]),        \
                   "r"(b0), "r"(b1))

#define CP_ASYNC16(dst, src)                                                  \
    asm volatile("cp.async.cg.shared.global [%0], [%1], 16;"                  \
                 :: "r"(dst), "l"(src))
#define CP_COMMIT()  asm volatile("cp.async.commit_group;")
#define CP_WAIT0()   asm volatile("cp.async.wait_group 0;" ::: "memory")

// ---- prep: fold BN scale into W, transpose, split bf16 hi/lo, k-chunk tile ----
__global__ void prep_W_kernel(const float* __restrict__ W,
                              const float* __restrict__ gamma,
                              const float* __restrict__ mvar) {
    int e = blockIdx.x * 256 + threadIdx.x;       // 0 .. 512*512-1
    int n = e & 511;
    int k = e >> 9;
    float s = gamma[n] * rsqrtf(mvar[n] + BN_EPS);
    float v = W[(size_t)k * FDIM + n] * s;
    __nv_bfloat16 h = __float2bfloat16(v);
    __nv_bfloat16 l = __float2bfloat16(v - __bfloat162float(h));
    int kc = k >> 4, kk = k & 15;
    size_t idx = (size_t)kc * (FDIM * 16) + n * 16 + kk;
    g_WT_hi[idx] = h;
    g_WT_lo[idx] = l;
}

// ---- main fused kernel ----
__global__ __launch_bounds__(THREADS, 1)
void fused_mma_sparsemax(const float* __restrict__ x,
                         const float* __restrict__ bias,
                         const float* __restrict__ gamma,
                         const float* __restrict__ beta,
                         const float* __restrict__ mmean,
                         const float* __restrict__ mvar,
                         float* __restrict__ out)
{
    extern __shared__ char smem[];
    const uint32_t sb = smem_u32(smem);
    const int tid  = threadIdx.x;
    const int wid  = tid >> 5;
    const int lane = tid & 31;
    const int r0   = blockIdx.x * BM;

    float acc[4][8][4];
    #pragma unroll
    for (int i = 0; i < 4; i++)
        #pragma unroll
        for (int j = 0; j < 8; j++)
            #pragma unroll
            for (int q = 0; q < 4; q++) acc[i][j][q] = 0.0f;

    // A loader: 256 threads, 1 float4 each (64 rows x 16 k per kstep)
    const int am  = tid >> 2;             // 0..63
    const int akq = tid & 3;              // float4 within row (k = 4*akq)

    // ldmatrix lane addressing (shared by A and B tiles)
    const int lrow = (lane & 7) + ((lane >> 3) & 1) * 8;
    const int lkc  = (lane >> 4) & 1;

    // ---- prologue: fill buffer 0
    {
        // B chunk copies (hi + lo): 4 chunks each per thread
        const char* srcH = (const char*)g_WT_hi;       // kstep 0
        const char* srcL = (const char*)g_WT_lo;
        #pragma unroll
        for (int i = 0; i < 4; i++) {
            int c = tid + i * 256;                      // 0..1023
            int n = c >> 1, kc = c & 1;
            CP_ASYNC16(sb + B_HI_OFF(0) + TOFF(n, kc), srcH + n * 32 + kc * 16);
            CP_ASYNC16(sb + B_LO_OFF(0) + TOFF(n, kc), srcL + n * 32 + kc * 16);
        }
        CP_COMMIT();

        float4 v = *reinterpret_cast<const float4*>(&x[(size_t)(r0 + am) * FDIM + akq * 4]);
        __nv_bfloat16 h0 = __float2bfloat16(v.x), h1 = __float2bfloat16(v.y);
        __nv_bfloat16 h2 = __float2bfloat16(v.z), h3 = __float2bfloat16(v.w);
        __nv_bfloat16 l0 = __float2bfloat16(v.x - __bfloat162float(h0));
        __nv_bfloat16 l1 = __float2bfloat16(v.y - __bfloat162float(h1));
        __nv_bfloat16 l2 = __float2bfloat16(v.z - __bfloat162float(h2));
        __nv_bfloat16 l3 = __float2bfloat16(v.w - __bfloat162float(h3));
        uint2 H, L;
        H.x = (uint32_t)__bfloat16_as_ushort(h0) | ((uint32_t)__bfloat16_as_ushort(h1) << 16);
        H.y = (uint32_t)__bfloat16_as_ushort(h2) | ((uint32_t)__bfloat16_as_ushort(h3) << 16);
        L.x = (uint32_t)__bfloat16_as_ushort(l0) | ((uint32_t)__bfloat16_as_ushort(l1) << 16);
        L.y = (uint32_t)__bfloat16_as_ushort(l2) | ((uint32_t)__bfloat16_as_ushort(l3) << 16);
        int off = TOFF(am, akq >> 1) + (akq & 1) * 8;
        *reinterpret_cast<uint2*>(smem + A_HI_OFF(0) + off) = H;
        *reinterpret_cast<uint2*>(smem + A_LO_OFF(0) + off) = L;

        CP_WAIT0();
        __syncthreads();
    }

    // ---- main loop over 32 k-steps
    for (int t = 0; t < KSTEPS; t++) {
        const int buf = t & 1;
        float4 nv;
        const bool more = (t + 1 < KSTEPS);

        if (more) {
            // issue next x row-chunk load (latency hidden by compute)
            nv = *reinterpret_cast<const float4*>(
                &x[(size_t)(r0 + am) * FDIM + (t + 1) * 16 + akq * 4]);
            // next W tiles via cp.async
            const char* srcH = (const char*)g_WT_hi + (size_t)(t + 1) * (FDIM * 16 * 2);
            const char* srcL = (const char*)g_WT_lo + (size_t)(t + 1) * (FDIM * 16 * 2);
            #pragma unroll
            for (int i = 0; i < 4; i++) {
                int c = tid + i * 256;
                int n = c >> 1, kc = c & 1;
                CP_ASYNC16(sb + B_HI_OFF(buf ^ 1) + TOFF(n, kc), srcH + n * 32 + kc * 16);
                CP_ASYNC16(sb + B_LO_OFF(buf ^ 1) + TOFF(n, kc), srcL + n * 32 + kc * 16);
            }
            CP_COMMIT();
        }

        // ---- compute current k-step
        uint32_t aH[4][4], aL[4][4];
        #pragma unroll
        for (int mt = 0; mt < 4; mt++) {
            int r = mt * 16 + lrow;
            LDSM4(aH[mt], sb + A_HI_OFF(buf) + TOFF(r, lkc));
            LDSM4(aL[mt], sb + A_LO_OFF(buf) + TOFF(r, lkc));
        }
        #pragma unroll
        for (int ntp = 0; ntp < 4; ntp++) {
            uint32_t bh[4], bl[4];
            int n = wid * 64 + ntp * 16 + lrow;
            LDSM4(bh, sb + B_HI_OFF(buf) + TOFF(n, lkc));
            LDSM4(bl, sb + B_LO_OFF(buf) + TOFF(n, lkc));
            #pragma unroll
            for (int mt = 0; mt < 4; mt++) {
                MMA16816(acc[mt][2 * ntp],     aH[mt], bh[0], bh[2]);
                MMA16816(acc[mt][2 * ntp + 1], aH[mt], bh[1], bh[3]);
                MMA16816(acc[mt][2 * ntp],     aH[mt], bl[0], bl[2]);
                MMA16816(acc[mt][2 * ntp + 1], aH[mt], bl[1], bl[3]);
                MMA16816(acc[mt][2 * ntp],     aL[mt], bh[0], bh[2]);
                MMA16816(acc[mt][2 * ntp + 1], aL[mt], bh[1], bh[3]);
            }
        }

        if (more) {
            // convert + store next A tile into the other buffer
            __nv_bfloat16 h0 = __float2bfloat16(nv.x), h1 = __float2bfloat16(nv.y);
            __nv_bfloat16 h2 = __float2bfloat16(nv.z), h3 = __float2bfloat16(nv.w);
            __nv_bfloat16 l0 = __float2bfloat16(nv.x - __bfloat162float(h0));
            __nv_bfloat16 l1 = __float2bfloat16(nv.y - __bfloat162float(h1));
            __nv_bfloat16 l2 = __float2bfloat16(nv.z - __bfloat162float(h2));
            __nv_bfloat16 l3 = __float2bfloat16(nv.w - __bfloat162float(h3));
            uint2 H, L;
            H.x = (uint32_t)__bfloat16_as_ushort(h0) | ((uint32_t)__bfloat16_as_ushort(h1) << 16);
            H.y = (uint32_t)__bfloat16_as_ushort(h2) | ((uint32_t)__bfloat16_as_ushort(h3) << 16);
            L.x = (uint32_t)__bfloat16_as_ushort(l0) | ((uint32_t)__bfloat16_as_ushort(l1) << 16);
            L.y = (uint32_t)__bfloat16_as_ushort(l2) | ((uint32_t)__bfloat16_as_ushort(l3) << 16);
            int off = TOFF(am, akq >> 1) + (akq & 1) * 8;
            *reinterpret_cast<uint2*>(smem + A_HI_OFF(buf ^ 1) + off) = H;
            *reinterpret_cast<uint2*>(smem + A_LO_OFF(buf ^ 1) + off) = L;
        }

        CP_WAIT0();
        __syncthreads();
    }

    // ---- stage accumulators to SMEM (unions over the GEMM buffers; all
    //      computes are past the loop-end __syncthreads)
    float* stage = reinterpret_cast<float*>(smem);
    #pragma unroll
    for (int mt = 0; mt < 4; mt++) {
        #pragma unroll
        for (int nt = 0; nt < 8; nt++) {
            int row = mt * 16 + (lane >> 2);
            int col = wid * 64 + nt * 8 + (lane & 3) * 2;
            float2 v01 = make_float2(acc[mt][nt][0], acc[mt][nt][1]);
            float2 v23 = make_float2(acc[mt][nt][2], acc[mt][nt][3]);
            *reinterpret_cast<float2*>(&stage[row * STG_STRIDE + col]) = v01;
            *reinterpret_cast<float2*>(&stage[(row + 8) * STG_STRIDE + col]) = v23;
        }
    }
    __syncthreads();

    // ---- epilogue: BN shift + sparsemax, 8 rows per warp, 16 cols per lane
    float shf[16];
    #pragma unroll
    for (int j = 0; j < 16; j++) {
        int f = lane + 32 * j;
        float s = gamma[f] * rsqrtf(mvar[f] + BN_EPS);
        shf[j] = fmaf(bias[f] - mmean[f], s, beta[f]);
    }

    #pragma unroll 1
    for (int i = 0; i < 8; i++) {
        const int row = wid * 8 + i;
        float z[16];
        #pragma unroll
        for (int j = 0; j < 16; j++)
            z[j] = stage[row * STG_STRIDE + lane + 32 * j] + shf[j];

        float m = -1e30f;
        #pragma unroll
        for (int j = 0; j < 16; j++) m = fmaxf(m, z[j]);
        #pragma unroll
        for (int off = 16; off > 0; off >>= 1)
            m = fmaxf(m, __shfl_xor_sync(0xFFFFFFFFu, m, off));

        float lo = m - 1.0f, hi = m;
        #pragma unroll 1
        for (int it = 0; it < 25; it++) {
            float tau = 0.5f * (lo + hi);
            float s = 0.0f;
            #pragma unroll
            for (int j = 0; j < 16; j++) s += fmaxf(z[j] - tau, 0.0f);
            #pragma unroll
            for (int off = 16; off > 0; off >>= 1)
                s += __shfl_xor_sync(0xFFFFFFFFu, s, off);
            if (s >= 1.0f) lo = tau; else hi = tau;
        }
        float tau = 0.5f * (lo + hi);

        float* orow = out + (size_t)(r0 + row) * FDIM;
        #pragma unroll
        for (int j = 0; j < 16; j++)
            orow[lane + 32 * j] = fmaxf(z[j] - tau, 0.0f);
    }
}

extern "C" void kernel_launch(void* const* d_in, const int* in_sizes, int n_in,
                              void* d_out, int out_size)
{
    const float* x     = (const float*)d_in[0];
    const float* W     = (const float*)d_in[1];
    const float* b     = (const float*)d_in[2];
    const float* gamma = (const float*)d_in[3];
    const float* beta  = (const float*)d_in[4];
    const float* mmean = (const float*)d_in[5];
    const float* mvar  = (const float*)d_in[6];
    float* out = (float*)d_out;

    cudaFuncSetAttribute(fused_mma_sparsemax,
                         cudaFuncAttributeMaxDynamicSharedMemorySize, SMEM_BYTES);

    int B = in_sizes[0] / FDIM;                 // 65536
    prep_W_kernel<<<(FDIM * FDIM) / 256, 256>>>(W, gamma, mvar);
    fused_mma_sparsemax<<<B / BM, THREADS, SMEM_BYTES>>>(x, b, gamma, beta, mmean, mvar, out);
}

// round 7
// speedup vs baseline: 2.6220x; 1.2372x over previous
#include <cuda_runtime.h>
#include <cuda_bf16.h>
#include <cstdint>

// Fused sparsemax(BN(x @ W + b)) via warp-level mma.sync, bf16 hi/lo split
// (3 passes, fp32 accum).  R7: prep-split of x (no in-loop conversion),
// 3-stage cp.async pipeline, Michelot fixed-point sparsemax epilogue.

#define FDIM 512
#define BM 64
#define THREADS 256
#define KSTEPS 32
#define BN_EPS 1e-5f
#define STG_STRIDE 520                  // 512 + 8 pad floats

// ---- device scratch (static, no allocation) ----
__device__ __align__(128) __nv_bfloat16 g_WT_hi[FDIM * FDIM];   // [kc][n][16]
__device__ __align__(128) __nv_bfloat16 g_WT_lo[FDIM * FDIM];
__device__ __align__(128) __nv_bfloat16 g_X_hi[65536ULL * FDIM]; // [kc][m][16]
__device__ __align__(128) __nv_bfloat16 g_X_lo[65536ULL * FDIM];

// ---- smem: 3 stages of 36 KB; epilogue stage region unions over them ----
#define STAGE_BYTES 36864
#define A_HI_O 0
#define A_LO_O 2048
#define B_HI_O 4096
#define B_LO_O 20480
#define SMEM_BYTES (BM * STG_STRIDE * 4)   // 133120 > 3*36864

// 16B-chunk swizzle inside a [rows][16 bf16] tile (8-row ldmatrix phase hits
// 8 distinct 16B slots of a 128B line).
#define TOFF(r, kc) (((((r) << 1) | (kc)) ^ (((r) >> 2) & 1)) << 4)

__device__ __forceinline__ uint32_t smem_u32(const void* p) {
    uint32_t a;
    asm("{ .reg .u64 t; cvta.to.shared.u64 t, %1; cvt.u32.u64 %0, t; }" : "=r"(a) : "l"(p));
    return a;
}

#define LDSM4(R, addr)                                                        \
    asm volatile("ldmatrix.sync.aligned.m8n8.x4.shared.b16 {%0,%1,%2,%3}, [%4];" \
                 : "=r"((R)[0]), "=r"((R)[1]), "=r"((R)[2]), "=r"((R)[3])     \
                 : "r"(addr))

#define MMA16816(d, a, b0, b1)                                                \
    asm volatile("mma.sync.aligned.m16n8k16.row.col.f32.bf16.bf16.f32 "       \
                 "{%0,%1,%2,%3},{%4,%5,%6,%7},{%8,%9},{%0,%1,%2,%3};"         \
                 : "+f"((d)[0]), "+f"((d)[1]), "+f"((d)[2]), "+f"((d)[3])     \
                 : "r"((a)[0]), "r"((a)[1]), "r"((a)[2]), "r"((a)[3]),        \
                   "r"(b0), "r"(b1))

#define CP_ASYNC16(dst, src)                                                  \
    asm volatile("cp.async.cg.shared.global [%0], [%1], 16;" :: "r"(dst), "l"(src))
#define CP_COMMIT()  asm volatile("cp.async.commit_group;")
#define CP_WAIT0()   asm volatile("cp.async.wait_group 0;" ::: "memory")
#define CP_WAIT1()   asm volatile("cp.async.wait_group 1;" ::: "memory")

__device__ __forceinline__ uint32_t pack_bf2(float a, float b) {
    __nv_bfloat16 x = __float2bfloat16(a), y = __float2bfloat16(b);
    return (uint32_t)__bfloat16_as_ushort(x) | ((uint32_t)__bfloat16_as_ushort(y) << 16);
}

// ---- prep W: fold BN scale, transpose, split hi/lo, kstep-tile ----
__global__ void prep_W_kernel(const float* __restrict__ W,
                              const float* __restrict__ gamma,
                              const float* __restrict__ mvar) {
    int e = blockIdx.x * 256 + threadIdx.x;
    int n = e & 511, k = e >> 9;
    float s = gamma[n] * rsqrtf(mvar[n] + BN_EPS);
    float v = W[(size_t)k * FDIM + n] * s;
    __nv_bfloat16 h = __float2bfloat16(v);
    __nv_bfloat16 l = __float2bfloat16(v - __bfloat162float(h));
    size_t idx = (size_t)(k >> 4) * (FDIM * 16) + n * 16 + (k & 15);
    g_WT_hi[idx] = h;
    g_WT_lo[idx] = l;
}

// ---- prep X: split x into bf16 hi/lo, kstep-tiled [kc][m][16] ----
__global__ void prep_X_kernel(const float* __restrict__ x) {
    int idx = blockIdx.x * 256 + threadIdx.x;   // 0 .. 65536*32-1
    int kc = idx >> 16;
    int m  = idx & 65535;
    const float4* src = reinterpret_cast<const float4*>(x + (size_t)m * FDIM + kc * 16);
    size_t base = (size_t)kc * (65536ULL * 16) + (size_t)m * 16;
    uint4* dh = reinterpret_cast<uint4*>(g_X_hi + base);
    uint4* dl = reinterpret_cast<uint4*>(g_X_lo + base);
    #pragma unroll
    for (int h = 0; h < 2; h++) {
        float4 v0 = src[2 * h], v1 = src[2 * h + 1];
        float f[8] = {v0.x, v0.y, v0.z, v0.w, v1.x, v1.y, v1.z, v1.w};
        uint4 H, L;
        uint32_t* hp = &H.x; uint32_t* lp = &L.x;
        #pragma unroll
        for (int p = 0; p < 4; p++) {
            float a = f[2 * p], b = f[2 * p + 1];
            __nv_bfloat16 ah = __float2bfloat16(a), bh = __float2bfloat16(b);
            hp[p] = (uint32_t)__bfloat16_as_ushort(ah) |
                    ((uint32_t)__bfloat16_as_ushort(bh) << 16);
            lp[p] = pack_bf2(a - __bfloat162float(ah), b - __bfloat162float(bh));
        }
        dh[h] = H;
        dl[h] = L;
    }
}

// ---- main fused kernel ----
__global__ __launch_bounds__(THREADS, 1)
void fused_mma_sparsemax(const float* __restrict__ bias,
                         const float* __restrict__ gamma,
                         const float* __restrict__ beta,
                         const float* __restrict__ mmean,
                         const float* __restrict__ mvar,
                         float* __restrict__ out)
{
    extern __shared__ char smem[];
    const uint32_t sb = smem_u32(smem);
    const int tid  = threadIdx.x;
    const int wid  = tid >> 5;
    const int lane = tid & 31;
    const int r0   = blockIdx.x * BM;

    float acc[4][8][4];
    #pragma unroll
    for (int i = 0; i < 4; i++)
        #pragma unroll
        for (int j = 0; j < 8; j++)
            #pragma unroll
            for (int q = 0; q < 4; q++) acc[i][j][q] = 0.0f;

    // A loader role: threads 0-127 -> hi, 128-255 -> lo; 1 chunk of 16B each
    const int a_half = tid >> 7;
    const int a_i    = tid & 127;            // chunk index: row=a_i>>1, c=a_i&1
    const __nv_bfloat16* a_base = a_half ? g_X_lo : g_X_hi;
    const char* a_src0 = (const char*)(a_base) + (size_t)(r0) * 32 + a_i * 16;
    const uint32_t a_dst = (a_half ? A_LO_O : A_HI_O) + TOFF(a_i >> 1, a_i & 1);

    // ldmatrix lane addressing
    const int lrow = (lane & 7) + ((lane >> 3) & 1) * 8;
    const int lkc  = (lane >> 4) & 1;
    const uint32_t t_base = TOFF(lrow, lkc);

    // per-kstep issue of all cp.async for stage s
    auto issue_stage = [&](int t, int s) {
        uint32_t stg = sb + s * STAGE_BYTES;
        // A hi or lo (1 chunk)
        CP_ASYNC16(stg + a_dst, a_src0 + (size_t)t * (65536ULL * 32));
        // B hi + lo (4 + 4 chunks)
        const char* srcH = (const char*)g_WT_hi + (size_t)t * 16384;
        const char* srcL = (const char*)g_WT_lo + (size_t)t * 16384;
        #pragma unroll
        for (int i = 0; i < 4; i++) {
            int c = tid + i * 256;          // 0..1023
            int n = c >> 1, kc = c & 1;
            CP_ASYNC16(stg + B_HI_O + TOFF(n, kc), srcH + c * 16);
            CP_ASYNC16(stg + B_LO_O + TOFF(n, kc), srcL + c * 16);
        }
    };

    // prologue: stages 0, 1
    issue_stage(0, 0); CP_COMMIT();
    issue_stage(1, 1); CP_COMMIT();

    for (int t = 0; t < KSTEPS; t++) {
        if (t < KSTEPS - 1) CP_WAIT1(); else CP_WAIT0();
        __syncthreads();
        if (t + 2 < KSTEPS) { issue_stage(t + 2, (t + 2) % 3); CP_COMMIT(); }

        const uint32_t stg = sb + (t % 3) * STAGE_BYTES;
        const uint32_t aH_b = stg + A_HI_O + t_base;
        const uint32_t aL_b = stg + A_LO_O + t_base;
        const uint32_t bH_b = stg + B_HI_O + t_base + wid * 2048;
        const uint32_t bL_b = stg + B_LO_O + t_base + wid * 2048;

        uint32_t aH[4][4], aL[4][4];
        #pragma unroll
        for (int mt = 0; mt < 4; mt++) {
            LDSM4(aH[mt], aH_b + mt * 512);
            LDSM4(aL[mt], aL_b + mt * 512);
        }
        #pragma unroll
        for (int ntp = 0; ntp < 4; ntp++) {
            uint32_t bh[4], bl[4];
            LDSM4(bh, bH_b + ntp * 512);
            LDSM4(bl, bL_b + ntp * 512);
            #pragma unroll
            for (int mt = 0; mt < 4; mt++) {
                MMA16816(acc[mt][2 * ntp],     aH[mt], bh[0], bh[2]);
                MMA16816(acc[mt][2 * ntp + 1], aH[mt], bh[1], bh[3]);
                MMA16816(acc[mt][2 * ntp],     aH[mt], bl[0], bl[2]);
                MMA16816(acc[mt][2 * ntp + 1], aH[mt], bl[1], bl[3]);
                MMA16816(acc[mt][2 * ntp],     aL[mt], bh[0], bh[2]);
                MMA16816(acc[mt][2 * ntp + 1], aL[mt], bh[1], bh[3]);
            }
        }
    }
    __syncthreads();

    // ---- stage accumulators to SMEM (stage region unions over GEMM buffers)
    float* stage = reinterpret_cast<float*>(smem);
    #pragma unroll
    for (int mt = 0; mt < 4; mt++) {
        #pragma unroll
        for (int nt = 0; nt < 8; nt++) {
            int row = mt * 16 + (lane >> 2);
            int col = wid * 64 + nt * 8 + (lane & 3) * 2;
            *reinterpret_cast<float2*>(&stage[row * STG_STRIDE + col]) =
                make_float2(acc[mt][nt][0], acc[mt][nt][1]);
            *reinterpret_cast<float2*>(&stage[(row + 8) * STG_STRIDE + col]) =
                make_float2(acc[mt][nt][2], acc[mt][nt][3]);
        }
    }
    __syncthreads();

    // ---- epilogue: BN shift + Michelot sparsemax, 8 rows/warp, 16 cols/lane
    float shf[16];
    #pragma unroll
    for (int j = 0; j < 16; j++) {
        int f = lane + 32 * j;
        float s = gamma[f] * rsqrtf(mvar[f] + BN_EPS);
        shf[j] = fmaf(bias[f] - mmean[f], s, beta[f]);
    }

    #pragma unroll 1
    for (int i = 0; i < 8; i++) {
        const int row = wid * 8 + i;
        float z[16];
        #pragma unroll
        for (int j = 0; j < 16; j++)
            z[j] = stage[row * STG_STRIDE + lane + 32 * j] + shf[j];

        float m = -1e30f;
        #pragma unroll
        for (int j = 0; j < 16; j++) m = fmaxf(m, z[j]);
        #pragma unroll
        for (int off = 16; off > 0; off >>= 1)
            m = fmaxf(m, __shfl_xor_sync(0xFFFFFFFFu, m, off));

        // Michelot fixed point: tau <- (sum_{z>tau} z - 1)/#{z>tau}; monotone
        // increasing from tau0 = m-1, converges to exact sparsemax tau.
        float tau = m - 1.0f;
        #pragma unroll 1
        for (int it = 0; it < 24; it++) {
            float S = 0.0f, K = 0.0f;
            #pragma unroll
            for (int j = 0; j < 16; j++) {
                if (z[j] > tau) { S += z[j]; K += 1.0f; }
            }
            #pragma unroll
            for (int off = 16; off > 0; off >>= 1) {
                S += __shfl_xor_sync(0xFFFFFFFFu, S, off);
                K += __shfl_xor_sync(0xFFFFFFFFu, K, off);
            }
            float nt = (S - 1.0f) / K;       // K >= 1 (z_max > tau always)
            bool done = !(nt > tau + 1e-7f); // warp-uniform (S,K reduced)
            tau = nt;
            if (done) break;
        }

        float* orow = out + (size_t)(r0 + row) * FDIM;
        #pragma unroll
        for (int j = 0; j < 16; j++)
            orow[lane + 32 * j] = fmaxf(z[j] - tau, 0.0f);
    }
}

extern "C" void kernel_launch(void* const* d_in, const int* in_sizes, int n_in,
                              void* d_out, int out_size)
{
    const float* x     = (const float*)d_in[0];
    const float* W     = (const float*)d_in[1];
    const float* b     = (const float*)d_in[2];
    const float* gamma = (const float*)d_in[3];
    const float* beta  = (const float*)d_in[4];
    const float* mmean = (const float*)d_in[5];
    const float* mvar  = (const float*)d_in[6];
    float* out = (float*)d_out;

    cudaFuncSetAttribute(fused_mma_sparsemax,
                         cudaFuncAttributeMaxDynamicSharedMemorySize, SMEM_BYTES);

    int B = in_sizes[0] / FDIM;                       // 65536
    prep_W_kernel<<<(FDIM * FDIM) / 256, 256>>>(W, gamma, mvar);
    prep_X_kernel<<<(B * (FDIM / 16)) / 256, 256>>>(x);
    fused_mma_sparsemax<<<B / BM, THREADS, SMEM_BYTES>>>(b, gamma, beta, mmean, mvar, out);
}

// round 8
// speedup vs baseline: 3.6349x; 1.3863x over previous
#include <cuda_runtime.h>
#include <cuda_fp16.h>
#include <cstdint>

// Fused sparsemax(BN(x @ W + b)) via warp-level mma.sync.
// R8: fp16 2-pass split (x = xh + xl fp16; W single fp16 with BN scale folded;
// only W-quant error remains ~2.4e-4 << 1e-3), 16 warps (warp tile 32x64),
// 3-stage cp.async pipeline, Michelot fixed-point sparsemax epilogue.

#define FDIM 512
#define BM 64
#define THREADS 512
#define KSTEPS 32
#define BN_EPS 1e-5f
#define STG_STRIDE 520                     // 512 + 8 pad floats

// ---- device scratch (static, no allocation) ----
__device__ __align__(128) __half g_WT[FDIM * FDIM];        // [kc][n][16] fp16
__device__ __align__(128) __half g_X_hi[65536ULL * FDIM];  // [kc][m][16]
__device__ __align__(128) __half g_X_lo[65536ULL * FDIM];

// ---- smem: 3 stages of 20 KB; epilogue stage region unions over them ----
#define STAGE_BYTES 20480
#define A_HI_O 0
#define A_LO_O 2048
#define B_O    4096
#define SMEM_BYTES (BM * STG_STRIDE * 4)   // 133120 > 3*20480

// 16B-chunk swizzle inside a [rows][16 fp16] tile (32 B per row; 8-row
// ldmatrix phase hits 8 distinct 16B slots of a 128B line).
#define TOFF(r, c) (((((r) << 1) | (c)) ^ (((r) >> 2) & 1)) << 4)

__device__ __forceinline__ uint32_t smem_u32(const void* p) {
    uint32_t a;
    asm("{ .reg .u64 t; cvta.to.shared.u64 t, %1; cvt.u32.u64 %0, t; }" : "=r"(a) : "l"(p));
    return a;
}

#define LDSM4(R, addr)                                                        \
    asm volatile("ldmatrix.sync.aligned.m8n8.x4.shared.b16 {%0,%1,%2,%3}, [%4];" \
                 : "=r"((R)[0]), "=r"((R)[1]), "=r"((R)[2]), "=r"((R)[3])     \
                 : "r"(addr))

#define MMA16816(d, a, b0, b1)                                                \
    asm volatile("mma.sync.aligned.m16n8k16.row.col.f32.f16.f16.f32 "         \
                 "{%0,%1,%2,%3},{%4,%5,%6,%7},{%8,%9},{%0,%1,%2,%3};"         \
                 : "+f"((d)[0]), "+f"((d)[1]), "+f"((d)[2]), "+f"((d)[3])     \
                 : "r"((a)[0]), "r"((a)[1]), "r"((a)[2]), "r"((a)[3]),        \
                   "r"(b0), "r"(b1))

#define CP_ASYNC16(dst, src)                                                  \
    asm volatile("cp.async.cg.shared.global [%0], [%1], 16;" :: "r"(dst), "l"(src))
#define CP_COMMIT()  asm volatile("cp.async.commit_group;")
#define CP_WAIT0()   asm volatile("cp.async.wait_group 0;" ::: "memory")
#define CP_WAIT1()   asm volatile("cp.async.wait_group 1;" ::: "memory")

// ---- prep W: fold BN scale, transpose, fp16, kstep-tile [kc][n][16] ----
__global__ void prep_W_kernel(const float* __restrict__ W,
                              const float* __restrict__ gamma,
                              const float* __restrict__ mvar) {
    int e = blockIdx.x * 256 + threadIdx.x;
    int n = e & 511, k = e >> 9;
    float s = gamma[n] * rsqrtf(mvar[n] + BN_EPS);
    float v = W[(size_t)k * FDIM + n] * s;
    g_WT[(size_t)(k >> 4) * (FDIM * 16) + n * 16 + (k & 15)] = __float2half_rn(v);
}

// ---- prep X: split x into fp16 hi/lo, kstep-tiled [kc][m][16] ----
__global__ void prep_X_kernel(const float* __restrict__ x) {
    int idx = blockIdx.x * 256 + threadIdx.x;   // 0 .. 65536*32-1
    int kc = idx >> 16;
    int m  = idx & 65535;
    const float4* src = reinterpret_cast<const float4*>(x + (size_t)m * FDIM + kc * 16);
    size_t base = (size_t)kc * (65536ULL * 16) + (size_t)m * 16;
    uint2* dh = reinterpret_cast<uint2*>(g_X_hi + base);
    uint2* dl = reinterpret_cast<uint2*>(g_X_lo + base);
    #pragma unroll
    for (int q = 0; q < 4; q++) {
        float4 v = src[q];
        float f[4] = {v.x, v.y, v.z, v.w};
        uint2 H, L;
        uint32_t* hp = &H.x; uint32_t* lp = &L.x;
        #pragma unroll
        for (int p = 0; p < 2; p++) {
            __half ah = __float2half_rn(f[2 * p]);
            __half bh = __float2half_rn(f[2 * p + 1]);
            __half al = __float2half_rn(f[2 * p]     - __half2float(ah));
            __half bl = __float2half_rn(f[2 * p + 1] - __half2float(bh));
            hp[p] = (uint32_t)__half_as_ushort(ah) | ((uint32_t)__half_as_ushort(bh) << 16);
            lp[p] = (uint32_t)__half_as_ushort(al) | ((uint32_t)__half_as_ushort(bl) << 16);
        }
        dh[q] = H;
        dl[q] = L;
    }
}

// ---- main fused kernel ----
__global__ __launch_bounds__(THREADS, 1)
void fused_mma_sparsemax(const float* __restrict__ bias,
                         const float* __restrict__ gamma,
                         const float* __restrict__ beta,
                         const float* __restrict__ mmean,
                         const float* __restrict__ mvar,
                         float* __restrict__ out)
{
    extern __shared__ char smem[];
    const uint32_t sb = smem_u32(smem);
    const int tid  = threadIdx.x;
    const int wid  = tid >> 5;
    const int lane = tid & 31;
    const int wr   = wid >> 3;            // warp row 0..1 (32 rows each)
    const int wc   = wid & 7;             // warp col 0..7 (64 cols each)
    const int r0   = blockIdx.x * BM;

    float acc[2][8][4];
    #pragma unroll
    for (int i = 0; i < 2; i++)
        #pragma unroll
        for (int j = 0; j < 8; j++)
            #pragma unroll
            for (int q = 0; q < 4; q++) acc[i][j][q] = 0.0f;

    // A loader: threads 0..255, chunk i = tid&127 of hi (tid<128) or lo
    const bool a_on   = tid < 256;
    const int  a_half = (tid >> 7) & 1;
    const int  a_i    = tid & 127;         // row = a_i>>1, c = a_i&1
    const char* a_src0 = (const char*)(a_half ? g_X_lo : g_X_hi)
                       + (size_t)r0 * 32 + a_i * 16;
    const uint32_t a_dst = (a_half ? A_LO_O : A_HI_O) + TOFF(a_i >> 1, a_i & 1);

    // ldmatrix lane addressing
    const int lrow = (lane & 7) + ((lane >> 3) & 1) * 8;
    const int lkc  = (lane >> 4) & 1;
    const uint32_t t_base = TOFF(lrow, lkc);

    auto issue_stage = [&](int t, int s) {
        uint32_t stg = sb + s * STAGE_BYTES;
        if (a_on)
            CP_ASYNC16(stg + a_dst, a_src0 + (size_t)t * (65536ULL * 32));
        const char* srcB = (const char*)g_WT + (size_t)t * 16384;
        #pragma unroll
        for (int i = 0; i < 2; i++) {
            int c = tid + i * 512;          // 0..1023
            CP_ASYNC16(stg + B_O + TOFF(c >> 1, c & 1), srcB + c * 16);
        }
    };

    issue_stage(0, 0); CP_COMMIT();
    issue_stage(1, 1); CP_COMMIT();

    for (int t = 0; t < KSTEPS; t++) {
        if (t < KSTEPS - 1) CP_WAIT1(); else CP_WAIT0();
        __syncthreads();
        if (t + 2 < KSTEPS) { issue_stage(t + 2, (t + 2) % 3); CP_COMMIT(); }

        const uint32_t stg  = sb + (t % 3) * STAGE_BYTES;
        const uint32_t aH_b = stg + A_HI_O + t_base + wr * 1024;
        const uint32_t aL_b = stg + A_LO_O + t_base + wr * 1024;
        const uint32_t b_b  = stg + B_O    + t_base + wc * 2048;

        uint32_t aH[2][4], aL[2][4];
        #pragma unroll
        for (int mt = 0; mt < 2; mt++) {
            LDSM4(aH[mt], aH_b + mt * 512);
            LDSM4(aL[mt], aL_b + mt * 512);
        }
        #pragma unroll
        for (int ntp = 0; ntp < 4; ntp++) {
            uint32_t bb[4];
            LDSM4(bb, b_b + ntp * 512);
            #pragma unroll
            for (int mt = 0; mt < 2; mt++) {
                MMA16816(acc[mt][2 * ntp],     aH[mt], bb[0], bb[2]);
                MMA16816(acc[mt][2 * ntp + 1], aH[mt], bb[1], bb[3]);
                MMA16816(acc[mt][2 * ntp],     aL[mt], bb[0], bb[2]);
                MMA16816(acc[mt][2 * ntp + 1], aL[mt], bb[1], bb[3]);
            }
        }
    }
    __syncthreads();

    // ---- stage accumulators to SMEM (unions over GEMM stage buffers)
    float* stage = reinterpret_cast<float*>(smem);
    #pragma unroll
    for (int mt = 0; mt < 2; mt++) {
        #pragma unroll
        for (int nt = 0; nt < 8; nt++) {
            int row = wr * 32 + mt * 16 + (lane >> 2);
            int col = wc * 64 + nt * 8 + (lane & 3) * 2;
            *reinterpret_cast<float2*>(&stage[row * STG_STRIDE + col]) =
                make_float2(acc[mt][nt][0], acc[mt][nt][1]);
            *reinterpret_cast<float2*>(&stage[(row + 8) * STG_STRIDE + col]) =
                make_float2(acc[mt][nt][2], acc[mt][nt][3]);
        }
    }
    __syncthreads();

    // ---- epilogue: BN shift + Michelot sparsemax, 4 rows/warp, 16 cols/lane
    float shf[16];
    #pragma unroll
    for (int j = 0; j < 16; j++) {
        int f = lane + 32 * j;
        float s = gamma[f] * rsqrtf(mvar[f] + BN_EPS);
        shf[j] = fmaf(bias[f] - mmean[f], s, beta[f]);
    }

    #pragma unroll 1
    for (int i = 0; i < 4; i++) {
        const int row = wid * 4 + i;
        float z[16];
        #pragma unroll
        for (int j = 0; j < 16; j++)
            z[j] = stage[row * STG_STRIDE + lane + 32 * j] + shf[j];

        float m = -1e30f;
        #pragma unroll
        for (int j = 0; j < 16; j++) m = fmaxf(m, z[j]);
        #pragma unroll
        for (int off = 16; off > 0; off >>= 1)
            m = fmaxf(m, __shfl_xor_sync(0xFFFFFFFFu, m, off));

        // Michelot fixed point: tau <- (sum_{z>tau} z - 1)/#{z>tau}
        float tau = m - 1.0f;
        #pragma unroll 1
        for (int it = 0; it < 24; it++) {
            float S = 0.0f, K = 0.0f;
            #pragma unroll
            for (int j = 0; j < 16; j++) {
                if (z[j] > tau) { S += z[j]; K += 1.0f; }
            }
            #pragma unroll
            for (int off = 16; off > 0; off >>= 1) {
                S += __shfl_xor_sync(0xFFFFFFFFu, S, off);
                K += __shfl_xor_sync(0xFFFFFFFFu, K, off);
            }
            float nt = (S - 1.0f) / K;
            bool done = !(nt > tau + 1e-7f);  // warp-uniform
            tau = nt;
            if (done) break;
        }

        float* orow = out + (size_t)(r0 + row) * FDIM;
        #pragma unroll
        for (int j = 0; j < 16; j++)
            orow[lane + 32 * j] = fmaxf(z[j] - tau, 0.0f);
    }
}

extern "C" void kernel_launch(void* const* d_in, const int* in_sizes, int n_in,
                              void* d_out, int out_size)
{
    const float* x     = (const float*)d_in[0];
    const float* W     = (const float*)d_in[1];
    const float* b     = (const float*)d_in[2];
    const float* gamma = (const float*)d_in[3];
    const float* beta  = (const float*)d_in[4];
    const float* mmean = (const float*)d_in[5];
    const float* mvar  = (const float*)d_in[6];
    float* out = (float*)d_out;

    cudaFuncSetAttribute(fused_mma_sparsemax,
                         cudaFuncAttributeMaxDynamicSharedMemorySize, SMEM_BYTES);

    int B = in_sizes[0] / FDIM;                       // 65536
    prep_W_kernel<<<(FDIM * FDIM) / 256, 256>>>(W, gamma, mvar);
    prep_X_kernel<<<(B * (FDIM / 16)) / 256, 256>>>(x);
    fused_mma_sparsemax<<<B / BM, THREADS, SMEM_BYTES>>>(b, gamma, beta, mmean, mvar, out);
}

// round 9
// speedup vs baseline: 4.0807x; 1.1227x over previous
#include <cuda_runtime.h>
#include <cuda_fp16.h>
#include <cstdint>

// Fused sparsemax(BN(x @ W + b)) via warp-level mma.sync.
// R9: fp16 2-pass (x = xh + xl in-kernel split; W single fp16, BN folded),
// no prep_X (direct LDG + in-register convert, one stage ahead),
// double-kstep stages (K=32/stage, 16 barrier iterations), 3-stage cp.async
// pipeline for W, 16 warps (warp tile 32x64), Michelot sparsemax epilogue.

#define FDIM 512
#define BM 64
#define THREADS 512
#define NSTAGE_IT 16                       // 16 iterations x 32 k each
#define BN_EPS 1e-5f
#define STG_STRIDE 520                     // 512 + 8 pad floats

// ---- device scratch (static, no allocation) ----
__device__ __align__(128) __half g_WT[FDIM * FDIM];   // [kc][n][16] fp16, BN-folded

// ---- smem: 3 stages of 40 KB; epilogue region unions over them ----
#define STAGE_BYTES 40960
#define A_HI_O 0                            // 2 ksteps x 2048
#define A_LO_O 4096
#define B_O    8192                         // 2 ksteps x 16384
#define SMEM_BYTES (BM * STG_STRIDE * 4)    // 133120 > 3*40960

// 16B-chunk swizzle inside a [rows][16 fp16] tile (8-row ldmatrix phase
// hits 8 distinct 16B slots of a 128B line).
#define TOFF(r, c) (((((r) << 1) | (c)) ^ (((r) >> 2) & 1)) << 4)

__device__ __forceinline__ uint32_t smem_u32(const void* p) {
    uint32_t a;
    asm("{ .reg .u64 t; cvta.to.shared.u64 t, %1; cvt.u32.u64 %0, t; }" : "=r"(a) : "l"(p));
    return a;
}

#define LDSM4(R, addr)                                                        \
    asm volatile("ldmatrix.sync.aligned.m8n8.x4.shared.b16 {%0,%1,%2,%3}, [%4];" \
                 : "=r"((R)[0]), "=r"((R)[1]), "=r"((R)[2]), "=r"((R)[3])     \
                 : "r"(addr))

#define MMA16816(d, a, b0, b1)                                                \
    asm volatile("mma.sync.aligned.m16n8k16.row.col.f32.f16.f16.f32 "         \
                 "{%0,%1,%2,%3},{%4,%5,%6,%7},{%8,%9},{%0,%1,%2,%3};"         \
                 : "+f"((d)[0]), "+f"((d)[1]), "+f"((d)[2]), "+f"((d)[3])     \
                 : "r"((a)[0]), "r"((a)[1]), "r"((a)[2]), "r"((a)[3]),        \
                   "r"(b0), "r"(b1))

#define CP_ASYNC16(dst, src)                                                  \
    asm volatile("cp.async.cg.shared.global [%0], [%1], 16;" :: "r"(dst), "l"(src))
#define CP_COMMIT()  asm volatile("cp.async.commit_group;")
#define CP_WAIT0()   asm volatile("cp.async.wait_group 0;" ::: "memory")
#define CP_WAIT1()   asm volatile("cp.async.wait_group 1;" ::: "memory")

// ---- prep W: fold BN scale, transpose, fp16, kstep-tile [kc][n][16] ----
__global__ void prep_W_kernel(const float* __restrict__ W,
                              const float* __restrict__ gamma,
                              const float* __restrict__ mvar) {
    int e = blockIdx.x * 256 + threadIdx.x;
    int n = e & 511, k = e >> 9;
    float s = gamma[n] * rsqrtf(mvar[n] + BN_EPS);
    float v = W[(size_t)k * FDIM + n] * s;
    g_WT[(size_t)(k >> 4) * (FDIM * 16) + n * 16 + (k & 15)] = __float2half_rn(v);
}

// ---- main fused kernel ----
__global__ __launch_bounds__(THREADS, 1)
void fused_mma_sparsemax(const float* __restrict__ x,
                         const float* __restrict__ bias,
                         const float* __restrict__ gamma,
                         const float* __restrict__ beta,
                         const float* __restrict__ mmean,
                         const float* __restrict__ mvar,
                         float* __restrict__ out)
{
    extern __shared__ char smem[];
    const uint32_t sb = smem_u32(smem);
    const int tid  = threadIdx.x;
    const int wid  = tid >> 5;
    const int lane = tid & 31;
    const int wr   = wid >> 3;             // warp row 0..1 (32 rows each)
    const int wc   = wid & 7;              // warp col 0..7 (64 cols each)
    const int r0   = blockIdx.x * BM;

    float acc[2][8][4];
    #pragma unroll
    for (int i = 0; i < 2; i++)
        #pragma unroll
        for (int j = 0; j < 8; j++)
            #pragma unroll
            for (int q = 0; q < 4; q++) acc[i][j][q] = 0.0f;

    // ---- A conversion role: thread -> (row, 4 consecutive k) of a 64x32 stage
    const int cv_row = tid >> 3;           // 0..63
    const int cv_k   = (tid & 7) * 4;      // 0,4,...,28
    const int cv_ks  = cv_k >> 4;          // kstep within stage
    const int cv_kk  = cv_k & 15;
    const uint32_t cv_off = cv_ks * 2048 + TOFF(cv_row, cv_kk >> 3) + (cv_kk & 7) * 2;
    const float* cv_src = x + (size_t)(r0 + cv_row) * FDIM + cv_k;

    // convert 4 fp32 -> hi/lo half2 pairs and store to stage buffer s
    auto cvt_sts = [&](float4 v, int s) {
        char* stg = smem + s * STAGE_BYTES;
        __half2 h01 = __floats2half2_rn(v.x, v.y);
        __half2 h23 = __floats2half2_rn(v.z, v.w);
        __half2 l01 = __floats2half2_rn(v.x - __half2float(__low2half(h01)),
                                        v.y - __half2float(__high2half(h01)));
        __half2 l23 = __floats2half2_rn(v.z - __half2float(__low2half(h23)),
                                        v.w - __half2float(__high2half(h23)));
        *reinterpret_cast<__half2*>(stg + A_HI_O + cv_off)     = h01;
        *reinterpret_cast<__half2*>(stg + A_HI_O + cv_off + 4) = h23;
        *reinterpret_cast<__half2*>(stg + A_LO_O + cv_off)     = l01;
        *reinterpret_cast<__half2*>(stg + A_LO_O + cv_off + 4) = l23;
    };

    // ---- B loader: 4 x 16B chunks per thread per stage (2 ksteps)
    auto issue_B = [&](int t, int s) {     // t = stage index (32 k each)
        uint32_t stg = sb + s * STAGE_BYTES;
        const char* srcB = (const char*)g_WT + (size_t)t * 32768;
        #pragma unroll
        for (int i = 0; i < 4; i++) {
            int c  = tid + i * 512;         // 0..2047
            int ks = c >> 10, w = c & 1023; // n = w>>1, chunk = w&1
            CP_ASYNC16(stg + B_O + ks * 16384 + TOFF(w >> 1, w & 1), srcB + c * 16);
        }
    };

    // ldmatrix lane addressing
    const int lrow = (lane & 7) + ((lane >> 3) & 1) * 8;
    const int lkc  = (lane >> 4) & 1;
    const uint32_t t_base = TOFF(lrow, lkc);

    // ---- prologue
    float4 a_cur;
    {
        float4 a0 = *reinterpret_cast<const float4*>(cv_src);          // stage 0
        cvt_sts(a0, 0);
        a_cur = *reinterpret_cast<const float4*>(cv_src + 32);         // stage 1
        issue_B(0, 0); CP_COMMIT();
        issue_B(1, 1); CP_COMMIT();
    }

    for (int t = 0; t < NSTAGE_IT; t++) {
        if (t < NSTAGE_IT - 1) CP_WAIT1(); else CP_WAIT0();
        __syncthreads();

        if (t + 2 < NSTAGE_IT) { issue_B(t + 2, (t + 2) % 3); CP_COMMIT(); }
        if (t + 1 < NSTAGE_IT) cvt_sts(a_cur, (t + 1) % 3);
        if (t + 2 < NSTAGE_IT)
            a_cur = *reinterpret_cast<const float4*>(cv_src + (t + 2) * 32);

        const uint32_t stg = sb + (t % 3) * STAGE_BYTES;
        #pragma unroll
        for (int ks = 0; ks < 2; ks++) {
            const uint32_t aH_b = stg + A_HI_O + ks * 2048 + t_base + wr * 1024;
            const uint32_t aL_b = stg + A_LO_O + ks * 2048 + t_base + wr * 1024;
            const uint32_t b_b  = stg + B_O    + ks * 16384 + t_base + wc * 2048;

            uint32_t aH[2][4], aL[2][4];
            #pragma unroll
            for (int mt = 0; mt < 2; mt++) {
                LDSM4(aH[mt], aH_b + mt * 512);
                LDSM4(aL[mt], aL_b + mt * 512);
            }
            #pragma unroll
            for (int ntp = 0; ntp < 4; ntp++) {
                uint32_t bb[4];
                LDSM4(bb, b_b + ntp * 512);
                #pragma unroll
                for (int mt = 0; mt < 2; mt++) {
                    MMA16816(acc[mt][2 * ntp],     aH[mt], bb[0], bb[2]);
                    MMA16816(acc[mt][2 * ntp + 1], aH[mt], bb[1], bb[3]);
                    MMA16816(acc[mt][2 * ntp],     aL[mt], bb[0], bb[2]);
                    MMA16816(acc[mt][2 * ntp + 1], aL[mt], bb[1], bb[3]);
                }
            }
        }
    }
    __syncthreads();

    // ---- stage accumulators to SMEM (unions over GEMM stage buffers)
    float* stage = reinterpret_cast<float*>(smem);
    #pragma unroll
    for (int mt = 0; mt < 2; mt++) {
        #pragma unroll
        for (int nt = 0; nt < 8; nt++) {
            int row = wr * 32 + mt * 16 + (lane >> 2);
            int col = wc * 64 + nt * 8 + (lane & 3) * 2;
            *reinterpret_cast<float2*>(&stage[row * STG_STRIDE + col]) =
                make_float2(acc[mt][nt][0], acc[mt][nt][1]);
            *reinterpret_cast<float2*>(&stage[(row + 8) * STG_STRIDE + col]) =
                make_float2(acc[mt][nt][2], acc[mt][nt][3]);
        }
    }
    __syncthreads();

    // ---- epilogue: BN shift + Michelot sparsemax, 4 rows/warp, 16 cols/lane
    float shf[16];
    #pragma unroll
    for (int j = 0; j < 16; j++) {
        int f = lane + 32 * j;
        float s = gamma[f] * rsqrtf(mvar[f] + BN_EPS);
        shf[j] = fmaf(bias[f] - mmean[f], s, beta[f]);
    }

    #pragma unroll 1
    for (int i = 0; i < 4; i++) {
        const int row = wid * 4 + i;
        float z[16];
        #pragma unroll
        for (int j = 0; j < 16; j++)
            z[j] = stage[row * STG_STRIDE + lane + 32 * j] + shf[j];

        float m = -1e30f;
        #pragma unroll
        for (int j = 0; j < 16; j++) m = fmaxf(m, z[j]);
        #pragma unroll
        for (int off = 16; off > 0; off >>= 1)
            m = fmaxf(m, __shfl_xor_sync(0xFFFFFFFFu, m, off));

        // Michelot fixed point: tau <- (sum_{z>tau} z - 1)/#{z>tau}
        float tau = m - 1.0f;
        #pragma unroll 1
        for (int it = 0; it < 24; it++) {
            float S = 0.0f, K = 0.0f;
            #pragma unroll
            for (int j = 0; j < 16; j++) {
                if (z[j] > tau) { S += z[j]; K += 1.0f; }
            }
            #pragma unroll
            for (int off = 16; off > 0; off >>= 1) {
                S += __shfl_xor_sync(0xFFFFFFFFu, S, off);
                K += __shfl_xor_sync(0xFFFFFFFFu, K, off);
            }
            float nt = (S - 1.0f) / K;
            bool done = !(nt > tau + 1e-7f);  // warp-uniform
            tau = nt;
            if (done) break;
        }

        float* orow = out + (size_t)(r0 + row) * FDIM;
        #pragma unroll
        for (int j = 0; j < 16; j++)
            orow[lane + 32 * j] = fmaxf(z[j] - tau, 0.0f);
    }
}

extern "C" void kernel_launch(void* const* d_in, const int* in_sizes, int n_in,
                              void* d_out, int out_size)
{
    const float* x     = (const float*)d_in[0];
    const float* W     = (const float*)d_in[1];
    const float* b     = (const float*)d_in[2];
    const float* gamma = (const float*)d_in[3];
    const float* beta  = (const float*)d_in[4];
    const float* mmean = (const float*)d_in[5];
    const float* mvar  = (const float*)d_in[6];
    float* out = (float*)d_out;

    cudaFuncSetAttribute(fused_mma_sparsemax,
                         cudaFuncAttributeMaxDynamicSharedMemorySize, SMEM_BYTES);

    int B = in_sizes[0] / FDIM;                       // 65536
    prep_W_kernel<<<(FDIM * FDIM) / 256, 256>>>(W, gamma, mvar);
    fused_mma_sparsemax<<<B / BM, THREADS, SMEM_BYTES>>>(x, b, gamma, beta, mmean, mvar, out);
}

// round 10
// speedup vs baseline: 4.1375x; 1.0139x over previous
#include <cuda_runtime.h>
#include <cuda_fp16.h>
#include <cstdint>

// Fused sparsemax(BN(x @ W + b)) via warp-level mma.sync.
// R10 = R9 + (a) hi/lo MMA passes separated to break same-acc dependency
// chains (distance 1 -> 7 issues), (b) hoisted cp.async addressing.
// fp16 2-pass: x = xh + xl (in-kernel split); W single fp16 with BN folded.

#define FDIM 512
#define BM 64
#define THREADS 512
#define NSTAGE_IT 16                       // 16 iterations x 32 k each
#define BN_EPS 1e-5f
#define STG_STRIDE 520                     // 512 + 8 pad floats

// ---- device scratch (static, no allocation) ----
__device__ __align__(128) __half g_WT[FDIM * FDIM];   // [kc][n][16] fp16, BN-folded

// ---- smem: 3 stages of 40 KB; epilogue region unions over them ----
#define STAGE_BYTES 40960
#define A_HI_O 0                            // 2 ksteps x 2048
#define A_LO_O 4096
#define B_O    8192                         // 2 ksteps x 16384
#define SMEM_BYTES (BM * STG_STRIDE * 4)    // 133120 > 3*40960

// 16B-chunk swizzle inside a [rows][16 fp16] tile (8-row ldmatrix phase
// hits 8 distinct 16B slots of a 128B line).
#define TOFF(r, c) (((((r) << 1) | (c)) ^ (((r) >> 2) & 1)) << 4)

__device__ __forceinline__ uint32_t smem_u32(const void* p) {
    uint32_t a;
    asm("{ .reg .u64 t; cvta.to.shared.u64 t, %1; cvt.u32.u64 %0, t; }" : "=r"(a) : "l"(p));
    return a;
}

#define LDSM4(R, addr)                                                        \
    asm volatile("ldmatrix.sync.aligned.m8n8.x4.shared.b16 {%0,%1,%2,%3}, [%4];" \
                 : "=r"((R)[0]), "=r"((R)[1]), "=r"((R)[2]), "=r"((R)[3])     \
                 : "r"(addr))

#define MMA16816(d, a, b0, b1)                                                \
    asm volatile("mma.sync.aligned.m16n8k16.row.col.f32.f16.f16.f32 "         \
                 "{%0,%1,%2,%3},{%4,%5,%6,%7},{%8,%9},{%0,%1,%2,%3};"         \
                 : "+f"((d)[0]), "+f"((d)[1]), "+f"((d)[2]), "+f"((d)[3])     \
                 : "r"((a)[0]), "r"((a)[1]), "r"((a)[2]), "r"((a)[3]),        \
                   "r"(b0), "r"(b1))

#define CP_ASYNC16(dst, src)                                                  \
    asm volatile("cp.async.cg.shared.global [%0], [%1], 16;" :: "r"(dst), "l"(src))
#define CP_COMMIT()  asm volatile("cp.async.commit_group;")
#define CP_WAIT0()   asm volatile("cp.async.wait_group 0;" ::: "memory")
#define CP_WAIT1()   asm volatile("cp.async.wait_group 1;" ::: "memory")

// ---- prep W: fold BN scale, transpose, fp16, kstep-tile [kc][n][16] ----
__global__ void prep_W_kernel(const float* __restrict__ W,
                              const float* __restrict__ gamma,
                              const float* __restrict__ mvar) {
    int e = blockIdx.x * 256 + threadIdx.x;
    int n = e & 511, k = e >> 9;
    float s = gamma[n] * rsqrtf(mvar[n] + BN_EPS);
    float v = W[(size_t)k * FDIM + n] * s;
    g_WT[(size_t)(k >> 4) * (FDIM * 16) + n * 16 + (k & 15)] = __float2half_rn(v);
}

// ---- main fused kernel ----
__global__ __launch_bounds__(THREADS, 1)
void fused_mma_sparsemax(const float* __restrict__ x,
                         const float* __restrict__ bias,
                         const float* __restrict__ gamma,
                         const float* __restrict__ beta,
                         const float* __restrict__ mmean,
                         const float* __restrict__ mvar,
                         float* __restrict__ out)
{
    extern __shared__ char smem[];
    const uint32_t sb = smem_u32(smem);
    const int tid  = threadIdx.x;
    const int wid  = tid >> 5;
    const int lane = tid & 31;
    const int wr   = wid >> 3;             // warp row 0..1 (32 rows each)
    const int wc   = wid & 7;              // warp col 0..7 (64 cols each)
    const int r0   = blockIdx.x * BM;

    float acc[2][8][4];
    #pragma unroll
    for (int i = 0; i < 2; i++)
        #pragma unroll
        for (int j = 0; j < 8; j++)
            #pragma unroll
            for (int q = 0; q < 4; q++) acc[i][j][q] = 0.0f;

    // ---- A conversion role: thread -> (row, 4 consecutive k) of a 64x32 stage
    const int cv_row = tid >> 3;           // 0..63
    const int cv_k   = (tid & 7) * 4;      // 0,4,...,28
    const uint32_t cv_off = (cv_k >> 4) * 2048 +
                            TOFF(cv_row, (cv_k & 15) >> 3) + (cv_k & 7) * 2;
    const float* cv_src = x + (size_t)(r0 + cv_row) * FDIM + cv_k;

    auto cvt_sts = [&](float4 v, int s) {
        char* stg = smem + s * STAGE_BYTES;
        __half2 h01 = __floats2half2_rn(v.x, v.y);
        __half2 h23 = __floats2half2_rn(v.z, v.w);
        __half2 l01 = __floats2half2_rn(v.x - __half2float(__low2half(h01)),
                                        v.y - __half2float(__high2half(h01)));
        __half2 l23 = __floats2half2_rn(v.z - __half2float(__low2half(h23)),
                                        v.w - __half2float(__high2half(h23)));
        *reinterpret_cast<__half2*>(stg + A_HI_O + cv_off)     = h01;
        *reinterpret_cast<__half2*>(stg + A_HI_O + cv_off + 4) = h23;
        *reinterpret_cast<__half2*>(stg + A_LO_O + cv_off)     = l01;
        *reinterpret_cast<__half2*>(stg + A_LO_O + cv_off + 4) = l23;
    };

    // ---- B loader: hoisted per-thread destination offsets (computed once)
    uint32_t b_dst[4];
    #pragma unroll
    for (int i = 0; i < 4; i++) {
        int c  = tid + i * 512;             // 0..2047
        int ks = c >> 10, w = c & 1023;     // n = w>>1, chunk = w&1
        b_dst[i] = B_O + ks * 16384 + TOFF(w >> 1, w & 1);
    }
    const char* b_src = (const char*)g_WT + (size_t)tid * 16;

    auto issue_B = [&](int t, int s) {      // t = stage index (32 k each)
        uint32_t stg = sb + s * STAGE_BYTES;
        const char* srcB = b_src + (size_t)t * 32768;
        #pragma unroll
        for (int i = 0; i < 4; i++)
            CP_ASYNC16(stg + b_dst[i], srcB + i * 512 * 16);
    };

    // ldmatrix lane addressing
    const int lrow = (lane & 7) + ((lane >> 3) & 1) * 8;
    const int lkc  = (lane >> 4) & 1;
    const uint32_t t_base = TOFF(lrow, lkc);

    // ---- prologue
    float4 a_cur;
    {
        float4 a0 = *reinterpret_cast<const float4*>(cv_src);          // stage 0
        cvt_sts(a0, 0);
        a_cur = *reinterpret_cast<const float4*>(cv_src + 32);         // stage 1
        issue_B(0, 0); CP_COMMIT();
        issue_B(1, 1); CP_COMMIT();
    }

    for (int t = 0; t < NSTAGE_IT; t++) {
        if (t < NSTAGE_IT - 1) CP_WAIT1(); else CP_WAIT0();
        __syncthreads();

        if (t + 2 < NSTAGE_IT) { issue_B(t + 2, (t + 2) % 3); CP_COMMIT(); }
        if (t + 1 < NSTAGE_IT) cvt_sts(a_cur, (t + 1) % 3);
        if (t + 2 < NSTAGE_IT)
            a_cur = *reinterpret_cast<const float4*>(cv_src + (t + 2) * 32);

        const uint32_t stg = sb + (t % 3) * STAGE_BYTES;
        #pragma unroll
        for (int ks = 0; ks < 2; ks++) {
            const uint32_t aH_b = stg + A_HI_O + ks * 2048 + t_base + wr * 1024;
            const uint32_t aL_b = stg + A_LO_O + ks * 2048 + t_base + wr * 1024;
            const uint32_t b_b  = stg + B_O    + ks * 16384 + t_base + wc * 2048;

            uint32_t aH[2][4], aL[2][4];
            #pragma unroll
            for (int mt = 0; mt < 2; mt++) {
                LDSM4(aH[mt], aH_b + mt * 512);
                LDSM4(aL[mt], aL_b + mt * 512);
            }
            #pragma unroll
            for (int g = 0; g < 2; g++) {       // ntp groups {0,1}, {2,3}
                uint32_t bb[2][4];
                LDSM4(bb[0], b_b + (2 * g + 0) * 512);
                LDSM4(bb[1], b_b + (2 * g + 1) * 512);
                // hi pass (8 MMAs), then lo pass (8 MMAs) -> same-acc
                // dependency distance 7 issues instead of 1
                #pragma unroll
                for (int p = 0; p < 2; p++) {
                    int ntp = 2 * g + p;
                    #pragma unroll
                    for (int mt = 0; mt < 2; mt++) {
                        MMA16816(acc[mt][2 * ntp],     aH[mt], bb[p][0], bb[p][2]);
                        MMA16816(acc[mt][2 * ntp + 1], aH[mt], bb[p][1], bb[p][3]);
                    }
                }
                #pragma unroll
                for (int p = 0; p < 2; p++) {
                    int ntp = 2 * g + p;
                    #pragma unroll
                    for (int mt = 0; mt < 2; mt++) {
                        MMA16816(acc[mt][2 * ntp],     aL[mt], bb[p][0], bb[p][2]);
                        MMA16816(acc[mt][2 * ntp + 1], aL[mt], bb[p][1], bb[p][3]);
                    }
                }
            }
        }
    }
    __syncthreads();

    // ---- stage accumulators to SMEM (unions over GEMM stage buffers)
    float* stage = reinterpret_cast<float*>(smem);
    #pragma unroll
    for (int mt = 0; mt < 2; mt++) {
        #pragma unroll
        for (int nt = 0; nt < 8; nt++) {
            int row = wr * 32 + mt * 16 + (lane >> 2);
            int col = wc * 64 + nt * 8 + (lane & 3) * 2;
            *reinterpret_cast<float2*>(&stage[row * STG_STRIDE + col]) =
                make_float2(acc[mt][nt][0], acc[mt][nt][1]);
            *reinterpret_cast<float2*>(&stage[(row + 8) * STG_STRIDE + col]) =
                make_float2(acc[mt][nt][2], acc[mt][nt][3]);
        }
    }
    __syncthreads();

    // ---- epilogue: BN shift + Michelot sparsemax, 4 rows/warp, 16 cols/lane
    float shf[16];
    #pragma unroll
    for (int j = 0; j < 16; j++) {
        int f = lane + 32 * j;
        float s = gamma[f] * rsqrtf(mvar[f] + BN_EPS);
        shf[j] = fmaf(bias[f] - mmean[f], s, beta[f]);
    }

    #pragma unroll 1
    for (int i = 0; i < 4; i++) {
        const int row = wid * 4 + i;
        float z[16];
        #pragma unroll
        for (int j = 0; j < 16; j++)
            z[j] = stage[row * STG_STRIDE + lane + 32 * j] + shf[j];

        float m = -1e30f;
        #pragma unroll
        for (int j = 0; j < 16; j++) m = fmaxf(m, z[j]);
        #pragma unroll
        for (int off = 16; off > 0; off >>= 1)
            m = fmaxf(m, __shfl_xor_sync(0xFFFFFFFFu, m, off));

        // Michelot fixed point: tau <- (sum_{z>tau} z - 1)/#{z>tau}
        float tau = m - 1.0f;
        #pragma unroll 1
        for (int it = 0; it < 24; it++) {
            float S = 0.0f, K = 0.0f;
            #pragma unroll
            for (int j = 0; j < 16; j++) {
                if (z[j] > tau) { S += z[j]; K += 1.0f; }
            }
            #pragma unroll
            for (int off = 16; off > 0; off >>= 1) {
                S += __shfl_xor_sync(0xFFFFFFFFu, S, off);
                K += __shfl_xor_sync(0xFFFFFFFFu, K, off);
            }
            float nt = (S - 1.0f) / K;
            bool done = !(nt > tau + 1e-7f);  // warp-uniform
            tau = nt;
            if (done) break;
        }

        float* orow = out + (size_t)(r0 + row) * FDIM;
        #pragma unroll
        for (int j = 0; j < 16; j++)
            orow[lane + 32 * j] = fmaxf(z[j] - tau, 0.0f);
    }
}

extern "C" void kernel_launch(void* const* d_in, const int* in_sizes, int n_in,
                              void* d_out, int out_size)
{
    const float* x     = (const float*)d_in[0];
    const float* W     = (const float*)d_in[1];
    const float* b     = (const float*)d_in[2];
    const float* gamma = (const float*)d_in[3];
    const float* beta  = (const float*)d_in[4];
    const float* mmean = (const float*)d_in[5];
    const float* mvar  = (const float*)d_in[6];
    float* out = (float*)d_out;

    cudaFuncSetAttribute(fused_mma_sparsemax,
                         cudaFuncAttributeMaxDynamicSharedMemorySize, SMEM_BYTES);

    int B = in_sizes[0] / FDIM;                       // 65536
    prep_W_kernel<<<(FDIM * FDIM) / 256, 256>>>(W, gamma, mvar);
    fused_mma_sparsemax<<<B / BM, THREADS, SMEM_BYTES>>>(x, b, gamma, beta, mmean, mvar, out);
}

// round 11
// speedup vs baseline: 4.5728x; 1.1052x over previous
#include <cuda_runtime.h>
#include <cuda_fp16.h>
#include <cstdint>

// Fused sparsemax(BN(x @ W + b)) via warp-level mma.sync.
// R11: BM=32 / 256 threads / SMEM 110.6 KB -> 2 CTAs/SM (occ 24.5% -> 50%),
// attacking the issue-latency bound (R10 showed dependency reorder is neutral;
// the binding constraint is warps-per-SMSP). fp16 2-pass: x = xh + xl
// (in-kernel split); W single fp16 with BN scale folded.

#define FDIM 512
#define BM 32
#define THREADS 256
#define NSTAGE_IT 16                       // 16 iterations x 32 k each
#define BN_EPS 1e-5f
#define STG_STRIDE 520                     // 512 + 8 pad floats

// ---- device scratch (static, no allocation) ----
__device__ __align__(128) __half g_WT[FDIM * FDIM];   // [kc][n][16] fp16, BN-folded

// ---- smem: 3 stages of 36 KB; epilogue region (66.5 KB) unions over them ----
#define STAGE_BYTES 36864
#define A_HI_O 0                            // 2 ksteps x 1024
#define A_LO_O 2048
#define B_O    4096                         // 2 ksteps x 16384
#define SMEM_BYTES (3 * STAGE_BYTES)        // 110592 (>= 32*520*4 = 66560)

// 16B-chunk swizzle inside a [rows][16 fp16] tile (8-row ldmatrix phase
// hits 8 distinct 16B slots of a 128B line).
#define TOFF(r, c) (((((r) << 1) | (c)) ^ (((r) >> 2) & 1)) << 4)

__device__ __forceinline__ uint32_t smem_u32(const void* p) {
    uint32_t a;
    asm("{ .reg .u64 t; cvta.to.shared.u64 t, %1; cvt.u32.u64 %0, t; }" : "=r"(a) : "l"(p));
    return a;
}

#define LDSM4(R, addr)                                                        \
    asm volatile("ldmatrix.sync.aligned.m8n8.x4.shared.b16 {%0,%1,%2,%3}, [%4];" \
                 : "=r"((R)[0]), "=r"((R)[1]), "=r"((R)[2]), "=r"((R)[3])     \
                 : "r"(addr))

#define MMA16816(d, a, b0, b1)                                                \
    asm volatile("mma.sync.aligned.m16n8k16.row.col.f32.f16.f16.f32 "         \
                 "{%0,%1,%2,%3},{%4,%5,%6,%7},{%8,%9},{%0,%1,%2,%3};"         \
                 : "+f"((d)[0]), "+f"((d)[1]), "+f"((d)[2]), "+f"((d)[3])     \
                 : "r"((a)[0]), "r"((a)[1]), "r"((a)[2]), "r"((a)[3]),        \
                   "r"(b0), "r"(b1))

#define CP_ASYNC16(dst, src)                                                  \
    asm volatile("cp.async.cg.shared.global [%0], [%1], 16;" :: "r"(dst), "l"(src))
#define CP_COMMIT()  asm volatile("cp.async.commit_group;")
#define CP_WAIT0()   asm volatile("cp.async.wait_group 0;" ::: "memory")
#define CP_WAIT1()   asm volatile("cp.async.wait_group 1;" ::: "memory")

// ---- prep W: fold BN scale, transpose, fp16, kstep-tile [kc][n][16] ----
__global__ void prep_W_kernel(const float* __restrict__ W,
                              const float* __restrict__ gamma,
                              const float* __restrict__ mvar) {
    int e = blockIdx.x * 256 + threadIdx.x;
    int n = e & 511, k = e >> 9;
    float s = gamma[n] * rsqrtf(mvar[n] + BN_EPS);
    float v = W[(size_t)k * FDIM + n] * s;
    g_WT[(size_t)(k >> 4) * (FDIM * 16) + n * 16 + (k & 15)] = __float2half_rn(v);
}

// ---- main fused kernel ----
__global__ __launch_bounds__(THREADS, 2)
void fused_mma_sparsemax(const float* __restrict__ x,
                         const float* __restrict__ bias,
                         const float* __restrict__ gamma,
                         const float* __restrict__ beta,
                         const float* __restrict__ mmean,
                         const float* __restrict__ mvar,
                         float* __restrict__ out)
{
    extern __shared__ char smem[];
    const uint32_t sb = smem_u32(smem);
    const int tid  = threadIdx.x;
    const int wid  = tid >> 5;             // warp col 0..7 (64 cols each)
    const int lane = tid & 31;
    const int r0   = blockIdx.x * BM;

    float acc[2][8][4];
    #pragma unroll
    for (int i = 0; i < 2; i++)
        #pragma unroll
        for (int j = 0; j < 8; j++)
            #pragma unroll
            for (int q = 0; q < 4; q++) acc[i][j][q] = 0.0f;

    // ---- A conversion role: thread -> (row, 4 consecutive k) of a 32x32 stage
    const int cv_row = tid >> 3;           // 0..31
    const int cv_k   = (tid & 7) * 4;      // 0,4,...,28
    const uint32_t cv_off = (cv_k >> 4) * 1024 +
                            TOFF(cv_row, (cv_k & 15) >> 3) + (cv_k & 7) * 2;
    const float* cv_src = x + (size_t)(r0 + cv_row) * FDIM + cv_k;

    auto cvt_sts = [&](float4 v, int s) {
        char* stg = smem + s * STAGE_BYTES;
        __half2 h01 = __floats2half2_rn(v.x, v.y);
        __half2 h23 = __floats2half2_rn(v.z, v.w);
        __half2 l01 = __floats2half2_rn(v.x - __half2float(__low2half(h01)),
                                        v.y - __half2float(__high2half(h01)));
        __half2 l23 = __floats2half2_rn(v.z - __half2float(__low2half(h23)),
                                        v.w - __half2float(__high2half(h23)));
        *reinterpret_cast<__half2*>(stg + A_HI_O + cv_off)     = h01;
        *reinterpret_cast<__half2*>(stg + A_HI_O + cv_off + 4) = h23;
        *reinterpret_cast<__half2*>(stg + A_LO_O + cv_off)     = l01;
        *reinterpret_cast<__half2*>(stg + A_LO_O + cv_off + 4) = l23;
    };

    // ---- B loader: 8 x 16B chunks per thread per stage (2 ksteps), hoisted
    uint32_t b_dst[8];
    #pragma unroll
    for (int i = 0; i < 8; i++) {
        int c  = tid + i * 256;             // 0..2047
        int ks = c >> 10, w = c & 1023;     // n = w>>1, chunk = w&1
        b_dst[i] = B_O + ks * 16384 + TOFF(w >> 1, w & 1);
    }
    const char* b_src = (const char*)g_WT + (size_t)tid * 16;

    auto issue_B = [&](int t, int s) {      // t = stage index (32 k each)
        uint32_t stg = sb + s * STAGE_BYTES;
        const char* srcB = b_src + (size_t)t * 32768;
        #pragma unroll
        for (int i = 0; i < 8; i++)
            CP_ASYNC16(stg + b_dst[i], srcB + i * 256 * 16);
    };

    // ldmatrix lane addressing
    const int lrow = (lane & 7) + ((lane >> 3) & 1) * 8;
    const int lkc  = (lane >> 4) & 1;
    const uint32_t t_base = TOFF(lrow, lkc);

    // ---- prologue
    float4 a_cur;
    {
        float4 a0 = *reinterpret_cast<const float4*>(cv_src);          // stage 0
        cvt_sts(a0, 0);
        a_cur = *reinterpret_cast<const float4*>(cv_src + 32);         // stage 1
        issue_B(0, 0); CP_COMMIT();
        issue_B(1, 1); CP_COMMIT();
    }

    for (int t = 0; t < NSTAGE_IT; t++) {
        if (t < NSTAGE_IT - 1) CP_WAIT1(); else CP_WAIT0();
        __syncthreads();

        if (t + 2 < NSTAGE_IT) { issue_B(t + 2, (t + 2) % 3); CP_COMMIT(); }
        if (t + 1 < NSTAGE_IT) cvt_sts(a_cur, (t + 1) % 3);
        if (t + 2 < NSTAGE_IT)
            a_cur = *reinterpret_cast<const float4*>(cv_src + (t + 2) * 32);

        const uint32_t stg = sb + (t % 3) * STAGE_BYTES;
        #pragma unroll
        for (int ks = 0; ks < 2; ks++) {
            const uint32_t aH_b = stg + A_HI_O + ks * 1024 + t_base;
            const uint32_t aL_b = stg + A_LO_O + ks * 1024 + t_base;
            const uint32_t b_b  = stg + B_O    + ks * 16384 + t_base + wid * 2048;

            uint32_t aH[2][4], aL[2][4];
            #pragma unroll
            for (int mt = 0; mt < 2; mt++) {
                LDSM4(aH[mt], aH_b + mt * 512);
                LDSM4(aL[mt], aL_b + mt * 512);
            }
            #pragma unroll
            for (int ntp = 0; ntp < 4; ntp++) {
                uint32_t bb[4];
                LDSM4(bb, b_b + ntp * 512);
                #pragma unroll
                for (int mt = 0; mt < 2; mt++) {
                    MMA16816(acc[mt][2 * ntp],     aH[mt], bb[0], bb[2]);
                    MMA16816(acc[mt][2 * ntp + 1], aH[mt], bb[1], bb[3]);
                    MMA16816(acc[mt][2 * ntp],     aL[mt], bb[0], bb[2]);
                    MMA16816(acc[mt][2 * ntp + 1], aL[mt], bb[1], bb[3]);
                }
            }
        }
    }
    __syncthreads();

    // ---- stage accumulators to SMEM (unions over GEMM stage buffers)
    float* stage = reinterpret_cast<float*>(smem);
    #pragma unroll
    for (int mt = 0; mt < 2; mt++) {
        #pragma unroll
        for (int nt = 0; nt < 8; nt++) {
            int row = mt * 16 + (lane >> 2);
            int col = wid * 64 + nt * 8 + (lane & 3) * 2;
            *reinterpret_cast<float2*>(&stage[row * STG_STRIDE + col]) =
                make_float2(acc[mt][nt][0], acc[mt][nt][1]);
            *reinterpret_cast<float2*>(&stage[(row + 8) * STG_STRIDE + col]) =
                make_float2(acc[mt][nt][2], acc[mt][nt][3]);
        }
    }
    __syncthreads();

    // ---- epilogue: BN shift + Michelot sparsemax, 4 rows/warp, 16 cols/lane
    float shf[16];
    #pragma unroll
    for (int j = 0; j < 16; j++) {
        int f = lane + 32 * j;
        float s = gamma[f] * rsqrtf(mvar[f] + BN_EPS);
        shf[j] = fmaf(bias[f] - mmean[f], s, beta[f]);
    }

    #pragma unroll 1
    for (int i = 0; i < 4; i++) {
        const int row = wid * 4 + i;
        float z[16];
        #pragma unroll
        for (int j = 0; j < 16; j++)
            z[j] = stage[row * STG_STRIDE + lane + 32 * j] + shf[j];

        float m = -1e30f;
        #pragma unroll
        for (int j = 0; j < 16; j++) m = fmaxf(m, z[j]);
        #pragma unroll
        for (int off = 16; off > 0; off >>= 1)
            m = fmaxf(m, __shfl_xor_sync(0xFFFFFFFFu, m, off));

        // Michelot fixed point: tau <- (sum_{z>tau} z - 1)/#{z>tau}
        float tau = m - 1.0f;
        #pragma unroll 1
        for (int it = 0; it < 24; it++) {
            float S = 0.0f, K = 0.0f;
            #pragma unroll
            for (int j = 0; j < 16; j++) {
                if (z[j] > tau) { S += z[j]; K += 1.0f; }
            }
            #pragma unroll
            for (int off = 16; off > 0; off >>= 1) {
                S += __shfl_xor_sync(0xFFFFFFFFu, S, off);
                K += __shfl_xor_sync(0xFFFFFFFFu, K, off);
            }
            float nt = (S - 1.0f) / K;
            bool done = !(nt > tau + 1e-7f);  // warp-uniform
            tau = nt;
            if (done) break;
        }

        float* orow = out + (size_t)(r0 + row) * FDIM;
        #pragma unroll
        for (int j = 0; j < 16; j++)
            orow[lane + 32 * j] = fmaxf(z[j] - tau, 0.0f);
    }
}

extern "C" void kernel_launch(void* const* d_in, const int* in_sizes, int n_in,
                              void* d_out, int out_size)
{
    const float* x     = (const float*)d_in[0];
    const float* W     = (const float*)d_in[1];
    const float* b     = (const float*)d_in[2];
    const float* gamma = (const float*)d_in[3];
    const float* beta  = (const float*)d_in[4];
    const float* mmean = (const float*)d_in[5];
    const float* mvar  = (const float*)d_in[6];
    float* out = (float*)d_out;

    cudaFuncSetAttribute(fused_mma_sparsemax,
                         cudaFuncAttributeMaxDynamicSharedMemorySize, SMEM_BYTES);

    int B = in_sizes[0] / FDIM;                       // 65536
    prep_W_kernel<<<(FDIM * FDIM) / 256, 256>>>(W, gamma, mvar);
    fused_mma_sparsemax<<<B / BM, THREADS, SMEM_BYTES>>>(x, b, gamma, beta, mmean, mvar, out);
}

// round 12
// speedup vs baseline: 4.7178x; 1.0317x over previous
#include <cuda_runtime.h>
#include <cuda_fp16.h>
#include <cstdint>

// Fused sparsemax(BN(x @ W + b)) via warp-level mma.sync.
// R12 = R11 + W tiles delivered by cp.async.bulk (one 32KB DMA per stage,
// single-thread issue, mbarrier complete_tx) instead of 8 cp.async per thread.
// W is PRE-SWIZZLED in gmem by prep_W so the linear bulk copy lands in the
// exact ldmatrix-friendly layout. Kills the LDGSTS issue/LSU storm.
// fp16 2-pass: x = xh + xl (in-kernel split); W single fp16 with BN folded.

#define FDIM 512
#define BM 32
#define THREADS 256
#define NSTAGE_IT 16                       // 16 iterations x 32 k each
#define BN_EPS 1e-5f
#define STG_STRIDE 520                     // 512 + 8 pad floats

// ---- device scratch (static, no allocation) ----
// g_WT holds W pre-swizzled: byte (k,n) -> (k>>4)*16384 + TOFF(n,(k&15)>>3) + (k&7)*2
__device__ __align__(128) __half g_WT[FDIM * FDIM];

// ---- smem: 3 stages of 36 KB + mbarriers; epilogue region unions stages ----
#define STAGE_BYTES 36864
#define A_HI_O 0                            // 2 ksteps x 1024
#define A_LO_O 2048
#define B_O    4096                         // 2 ksteps x 16384 (contiguous 32KB)
#define MBAR_O (3 * STAGE_BYTES)            // 110592: 3 x 8B mbarriers
#define SMEM_BYTES (MBAR_O + 64)            // 110656 (>= 32*520*4 = 66560)

// 16B-chunk swizzle inside a [rows][16 fp16] tile (8-row ldmatrix phase
// hits 8 distinct 16B slots of a 128B line).
#define TOFF(r, c) (((((r) << 1) | (c)) ^ (((r) >> 2) & 1)) << 4)

__device__ __forceinline__ uint32_t smem_u32(const void* p) {
    uint32_t a;
    asm("{ .reg .u64 t; cvta.to.shared.u64 t, %1; cvt.u32.u64 %0, t; }" : "=r"(a) : "l"(p));
    return a;
}

#define LDSM4(R, addr)                                                        \
    asm volatile("ldmatrix.sync.aligned.m8n8.x4.shared.b16 {%0,%1,%2,%3}, [%4];" \
                 : "=r"((R)[0]), "=r"((R)[1]), "=r"((R)[2]), "=r"((R)[3])     \
                 : "r"(addr))

#define MMA16816(d, a, b0, b1)                                                \
    asm volatile("mma.sync.aligned.m16n8k16.row.col.f32.f16.f16.f32 "         \
                 "{%0,%1,%2,%3},{%4,%5,%6,%7},{%8,%9},{%0,%1,%2,%3};"         \
                 : "+f"((d)[0]), "+f"((d)[1]), "+f"((d)[2]), "+f"((d)[3])     \
                 : "r"((a)[0]), "r"((a)[1]), "r"((a)[2]), "r"((a)[3]),        \
                   "r"(b0), "r"(b1))

#define MBARRIER_INIT(mb, c) \
    asm volatile("mbarrier.init.shared.b64 [%0], %1;" :: "r"((uint32_t)(mb)), "r"((uint32_t)(c)) : "memory")
#define MBARRIER_EXPECT_TX(mb, bytes) \
    asm volatile("mbarrier.arrive.expect_tx.shared.b64 _, [%0], %1;" \
                 :: "r"((uint32_t)(mb)), "r"((uint32_t)(bytes)) : "memory")
#define BULK_G2S(dst, src, size, mb)                                          \
    asm volatile("cp.async.bulk.shared::cta.global.mbarrier::complete_tx::bytes " \
                 "[%0], [%1], %2, [%3];"                                      \
                 :: "r"((uint32_t)(dst)), "l"(src), "r"((uint32_t)(size)),    \
                    "r"((uint32_t)(mb)) : "memory")
#define MBARRIER_WAIT_PARITY(mb, par) do {                                    \
    uint32_t _mb = (uint32_t)(mb), _pa = (uint32_t)(par), _dn;                \
    asm volatile("{\n\t.reg .pred p;\n\t"                                     \
        "mbarrier.try_wait.parity.acquire.cta.shared::cta.b64 p, [%1], %2;\n\t" \
        "selp.b32 %0, 1, 0, p;\n\t}" : "=r"(_dn) : "r"(_mb), "r"(_pa) : "memory"); \
    if (!_dn) {                                                               \
        asm volatile("{\n\t.reg .pred P1;\n\t"                                \
            "WL_%=:\n\t"                                                      \
            "mbarrier.try_wait.parity.acquire.cta.shared::cta.b64 P1, [%0], %1, 0x989680;\n\t" \
            "@P1 bra.uni WD_%=;\n\tbra.uni WL_%=;\n\tWD_%=:\n\t}"             \
            :: "r"(_mb), "r"(_pa) : "memory");                                \
    }                                                                         \
} while (0)

// ---- prep W: fold BN scale, transpose, fp16, PRE-SWIZZLED kstep tiles ----
__global__ void prep_W_kernel(const float* __restrict__ W,
                              const float* __restrict__ gamma,
                              const float* __restrict__ mvar) {
    int e = blockIdx.x * 256 + threadIdx.x;
    int n = e & 511, k = e >> 9;
    float s = gamma[n] * rsqrtf(mvar[n] + BN_EPS);
    float v = W[(size_t)k * FDIM + n] * s;
    size_t byte_off = (size_t)(k >> 4) * 16384
                    + TOFF(n, (k & 15) >> 3) + (k & 7) * 2;
    *reinterpret_cast<__half*>(reinterpret_cast<char*>(g_WT) + byte_off) =
        __float2half_rn(v);
}

// ---- main fused kernel ----
__global__ __launch_bounds__(THREADS, 2)
void fused_mma_sparsemax(const float* __restrict__ x,
                         const float* __restrict__ bias,
                         const float* __restrict__ gamma,
                         const float* __restrict__ beta,
                         const float* __restrict__ mmean,
                         const float* __restrict__ mvar,
                         float* __restrict__ out)
{
    extern __shared__ char smem[];
    const uint32_t sb = smem_u32(smem);
    const int tid  = threadIdx.x;
    const int wid  = tid >> 5;             // warp col 0..7 (64 cols each)
    const int lane = tid & 31;
    const int r0   = blockIdx.x * BM;

    float acc[2][8][4];
    #pragma unroll
    for (int i = 0; i < 2; i++)
        #pragma unroll
        for (int j = 0; j < 8; j++)
            #pragma unroll
            for (int q = 0; q < 4; q++) acc[i][j][q] = 0.0f;

    // ---- A conversion role: thread -> (row, 4 consecutive k) of a 32x32 stage
    const int cv_row = tid >> 3;           // 0..31
    const int cv_k   = (tid & 7) * 4;      // 0,4,...,28
    const uint32_t cv_off = (cv_k >> 4) * 1024 +
                            TOFF(cv_row, (cv_k & 15) >> 3) + (cv_k & 7) * 2;
    const float* cv_src = x + (size_t)(r0 + cv_row) * FDIM + cv_k;

    auto cvt_sts = [&](float4 v, int s) {
        char* stg = smem + s * STAGE_BYTES;
        __half2 h01 = __floats2half2_rn(v.x, v.y);
        __half2 h23 = __floats2half2_rn(v.z, v.w);
        __half2 l01 = __floats2half2_rn(v.x - __half2float(__low2half(h01)),
                                        v.y - __half2float(__high2half(h01)));
        __half2 l23 = __floats2half2_rn(v.z - __half2float(__low2half(h23)),
                                        v.w - __half2float(__high2half(h23)));
        *reinterpret_cast<__half2*>(stg + A_HI_O + cv_off)     = h01;
        *reinterpret_cast<__half2*>(stg + A_HI_O + cv_off + 4) = h23;
        *reinterpret_cast<__half2*>(stg + A_LO_O + cv_off)     = l01;
        *reinterpret_cast<__half2*>(stg + A_LO_O + cv_off + 4) = l23;
    };

    // ---- mbarrier init (one per stage) ----
    if (tid == 0) {
        MBARRIER_INIT(sb + MBAR_O + 0,  1);
        MBARRIER_INIT(sb + MBAR_O + 8,  1);
        MBARRIER_INIT(sb + MBAR_O + 16, 1);
    }
    __syncthreads();

    // ---- B DMA: one 32KB bulk copy per stage (pre-swizzled source) ----
    auto issue_B = [&](int t, int s) {      // t = stage index (32 k each)
        MBARRIER_EXPECT_TX(sb + MBAR_O + s * 8, 32768);
        BULK_G2S(sb + s * STAGE_BYTES + B_O,
                 (const char*)g_WT + (size_t)t * 32768,
                 32768, sb + MBAR_O + s * 8);
    };

    // ldmatrix lane addressing
    const int lrow = (lane & 7) + ((lane >> 3) & 1) * 8;
    const int lkc  = (lane >> 4) & 1;
    const uint32_t t_base = TOFF(lrow, lkc);

    // ---- prologue
    float4 a_cur;
    {
        if (tid == 0) { issue_B(0, 0); issue_B(1, 1); }
        float4 a0 = *reinterpret_cast<const float4*>(cv_src);          // stage 0
        cvt_sts(a0, 0);
        a_cur = *reinterpret_cast<const float4*>(cv_src + 32);         // stage 1
    }

    int ph0 = 0, ph1 = 0, ph2 = 0;
    for (int t = 0; t < NSTAGE_IT; t++) {
        const int s = t % 3;
        if (s == 0)      { MBARRIER_WAIT_PARITY(sb + MBAR_O + 0,  ph0); ph0 ^= 1; }
        else if (s == 1) { MBARRIER_WAIT_PARITY(sb + MBAR_O + 8,  ph1); ph1 ^= 1; }
        else             { MBARRIER_WAIT_PARITY(sb + MBAR_O + 16, ph2); ph2 ^= 1; }
        __syncthreads();   // A tile of stage s visible; prior readers of the
                           // stage being overwritten below are done

        if (t + 2 < NSTAGE_IT && tid == 0) issue_B(t + 2, (t + 2) % 3);
        if (t + 1 < NSTAGE_IT) cvt_sts(a_cur, (t + 1) % 3);
        if (t + 2 < NSTAGE_IT)
            a_cur = *reinterpret_cast<const float4*>(cv_src + (t + 2) * 32);

        const uint32_t stg = sb + s * STAGE_BYTES;
        #pragma unroll
        for (int ks = 0; ks < 2; ks++) {
            const uint32_t aH_b = stg + A_HI_O + ks * 1024 + t_base;
            const uint32_t aL_b = stg + A_LO_O + ks * 1024 + t_base;
            const uint32_t b_b  = stg + B_O    + ks * 16384 + t_base + wid * 2048;

            uint32_t aH[2][4], aL[2][4];
            #pragma unroll
            for (int mt = 0; mt < 2; mt++) {
                LDSM4(aH[mt], aH_b + mt * 512);
                LDSM4(aL[mt], aL_b + mt * 512);
            }
            #pragma unroll
            for (int ntp = 0; ntp < 4; ntp++) {
                uint32_t bb[4];
                LDSM4(bb, b_b + ntp * 512);
                #pragma unroll
                for (int mt = 0; mt < 2; mt++) {
                    MMA16816(acc[mt][2 * ntp],     aH[mt], bb[0], bb[2]);
                    MMA16816(acc[mt][2 * ntp + 1], aH[mt], bb[1], bb[3]);
                    MMA16816(acc[mt][2 * ntp],     aL[mt], bb[0], bb[2]);
                    MMA16816(acc[mt][2 * ntp + 1], aL[mt], bb[1], bb[3]);
                }
            }
        }
    }
    __syncthreads();

    // ---- stage accumulators to SMEM (unions over GEMM stage buffers)
    float* stage = reinterpret_cast<float*>(smem);
    #pragma unroll
    for (int mt = 0; mt < 2; mt++) {
        #pragma unroll
        for (int nt = 0; nt < 8; nt++) {
            int row = mt * 16 + (lane >> 2);
            int col = wid * 64 + nt * 8 + (lane & 3) * 2;
            *reinterpret_cast<float2*>(&stage[row * STG_STRIDE + col]) =
                make_float2(acc[mt][nt][0], acc[mt][nt][1]);
            *reinterpret_cast<float2*>(&stage[(row + 8) * STG_STRIDE + col]) =
                make_float2(acc[mt][nt][2], acc[mt][nt][3]);
        }
    }
    __syncthreads();

    // ---- epilogue: BN shift + Michelot sparsemax, 4 rows/warp, 16 cols/lane
    float shf[16];
    #pragma unroll
    for (int j = 0; j < 16; j++) {
        int f = lane + 32 * j;
        float s = gamma[f] * rsqrtf(mvar[f] + BN_EPS);
        shf[j] = fmaf(bias[f] - mmean[f], s, beta[f]);
    }

    #pragma unroll 1
    for (int i = 0; i < 4; i++) {
        const int row = wid * 4 + i;
        float z[16];
        #pragma unroll
        for (int j = 0; j < 16; j++)
            z[j] = stage[row * STG_STRIDE + lane + 32 * j] + shf[j];

        float m = -1e30f;
        #pragma unroll
        for (int j = 0; j < 16; j++) m = fmaxf(m, z[j]);
        #pragma unroll
        for (int off = 16; off > 0; off >>= 1)
            m = fmaxf(m, __shfl_xor_sync(0xFFFFFFFFu, m, off));

        // Michelot fixed point: tau <- (sum_{z>tau} z - 1)/#{z>tau}
        float tau = m - 1.0f;
        #pragma unroll 1
        for (int it = 0; it < 24; it++) {
            float S = 0.0f, K = 0.0f;
            #pragma unroll
            for (int j = 0; j < 16; j++) {
                if (z[j] > tau) { S += z[j]; K += 1.0f; }
            }
            #pragma unroll
            for (int off = 16; off > 0; off >>= 1) {
                S += __shfl_xor_sync(0xFFFFFFFFu, S, off);
                K += __shfl_xor_sync(0xFFFFFFFFu, K, off);
            }
            float nt = (S - 1.0f) / K;
            bool done = !(nt > tau + 1e-7f);  // warp-uniform
            tau = nt;
            if (done) break;
        }

        float* orow = out + (size_t)(r0 + row) * FDIM;
        #pragma unroll
        for (int j = 0; j < 16; j++)
            orow[lane + 32 * j] = fmaxf(z[j] - tau, 0.0f);
    }
}

extern "C" void kernel_launch(void* const* d_in, const int* in_sizes, int n_in,
                              void* d_out, int out_size)
{
    const float* x     = (const float*)d_in[0];
    const float* W     = (const float*)d_in[1];
    const float* b     = (const float*)d_in[2];
    const float* gamma = (const float*)d_in[3];
    const float* beta  = (const float*)d_in[4];
    const float* mmean = (const float*)d_in[5];
    const float* mvar  = (const float*)d_in[6];
    float* out = (float*)d_out;

    cudaFuncSetAttribute(fused_mma_sparsemax,
                         cudaFuncAttributeMaxDynamicSharedMemorySize, SMEM_BYTES);

    int B = in_sizes[0] / FDIM;                       // 65536
    prep_W_kernel<<<(FDIM * FDIM) / 256, 256>>>(W, gamma, mvar);
    fused_mma_sparsemax<<<B / BM, THREADS, SMEM_BYTES>>>(x, b, gamma, beta, mmean, mvar, out);
}

// round 13
// speedup vs baseline: 6.6073x; 1.4005x over previous
#include <cuda_runtime.h>
#include <cuda_fp16.h>
#include <cstdint>

// Fused sparsemax(BN(x @ W + b)) via warp-level mma.sync.
// R13 = R12 with the x-lo pass DROPPED: single fp16 pass (x fp16, W fp16 with
// BN scale folded). Halves MMA + LDSM work. Error model (calibrated on R8-R12:
// W-quant alone -> 5.39e-4): adding x-quant gives sqrt(2)*z-err ->
// predicted rel_err ~7.6e-4 < 1e-3.
// W tiles via cp.async.bulk DMA (pre-swizzled in gmem), 3-stage pipeline,
// BM=32 / 256 threads / 2 CTAs/SM, Michelot sparsemax epilogue.

#define FDIM 512
#define BM 32
#define THREADS 256
#define NSTAGE_IT 16                       // 16 iterations x 32 k each
#define BN_EPS 1e-5f
#define STG_STRIDE 520                     // 512 + 8 pad floats

// ---- device scratch (static, no allocation) ----
// g_WT holds W pre-swizzled: byte (k,n) -> (k>>4)*16384 + TOFF(n,(k&15)>>3) + (k&7)*2
__device__ __align__(128) __half g_WT[FDIM * FDIM];

// ---- smem: 3 stages of 34 KB + mbarriers; epilogue region unions stages ----
#define STAGE_BYTES 34816
#define A_O 0                               // 2 ksteps x 1024 = 2048
#define B_O 2048                            // 2 ksteps x 16384 (contiguous 32KB)
#define MBAR_O (3 * STAGE_BYTES)            // 104448: 3 x 8B mbarriers
#define SMEM_BYTES (MBAR_O + 64)            // 104512 (>= 32*520*4 = 66560)

// 16B-chunk swizzle inside a [rows][16 fp16] tile (8-row ldmatrix phase
// hits 8 distinct 16B slots of a 128B line).
#define TOFF(r, c) (((((r) << 1) | (c)) ^ (((r) >> 2) & 1)) << 4)

__device__ __forceinline__ uint32_t smem_u32(const void* p) {
    uint32_t a;
    asm("{ .reg .u64 t; cvta.to.shared.u64 t, %1; cvt.u32.u64 %0, t; }" : "=r"(a) : "l"(p));
    return a;
}

#define LDSM4(R, addr)                                                        \
    asm volatile("ldmatrix.sync.aligned.m8n8.x4.shared.b16 {%0,%1,%2,%3}, [%4];" \
                 : "=r"((R)[0]), "=r"((R)[1]), "=r"((R)[2]), "=r"((R)[3])     \
                 : "r"(addr))

#define MMA16816(d, a, b0, b1)                                                \
    asm volatile("mma.sync.aligned.m16n8k16.row.col.f32.f16.f16.f32 "         \
                 "{%0,%1,%2,%3},{%4,%5,%6,%7},{%8,%9},{%0,%1,%2,%3};"         \
                 : "+f"((d)[0]), "+f"((d)[1]), "+f"((d)[2]), "+f"((d)[3])     \
                 : "r"((a)[0]), "r"((a)[1]), "r"((a)[2]), "r"((a)[3]),        \
                   "r"(b0), "r"(b1))

#define MBARRIER_INIT(mb, c) \
    asm volatile("mbarrier.init.shared.b64 [%0], %1;" :: "r"((uint32_t)(mb)), "r"((uint32_t)(c)) : "memory")
#define MBARRIER_EXPECT_TX(mb, bytes) \
    asm volatile("mbarrier.arrive.expect_tx.shared.b64 _, [%0], %1;" \
                 :: "r"((uint32_t)(mb)), "r"((uint32_t)(bytes)) : "memory")
#define BULK_G2S(dst, src, size, mb)                                          \
    asm volatile("cp.async.bulk.shared::cta.global.mbarrier::complete_tx::bytes " \
                 "[%0], [%1], %2, [%3];"                                      \
                 :: "r"((uint32_t)(dst)), "l"(src), "r"((uint32_t)(size)),    \
                    "r"((uint32_t)(mb)) : "memory")
#define MBARRIER_WAIT_PARITY(mb, par) do {                                    \
    uint32_t _mb = (uint32_t)(mb), _pa = (uint32_t)(par), _dn;                \
    asm volatile("{\n\t.reg .pred p;\n\t"                                     \
        "mbarrier.try_wait.parity.acquire.cta.shared::cta.b64 p, [%1], %2;\n\t" \
        "selp.b32 %0, 1, 0, p;\n\t}" : "=r"(_dn) : "r"(_mb), "r"(_pa) : "memory"); \
    if (!_dn) {                                                               \
        asm volatile("{\n\t.reg .pred P1;\n\t"                                \
            "WL_%=:\n\t"                                                      \
            "mbarrier.try_wait.parity.acquire.cta.shared::cta.b64 P1, [%0], %1, 0x989680;\n\t" \
            "@P1 bra.uni WD_%=;\n\tbra.uni WL_%=;\n\tWD_%=:\n\t}"             \
            :: "r"(_mb), "r"(_pa) : "memory");                                \
    }                                                                         \
} while (0)

// ---- prep W: fold BN scale, transpose, fp16, PRE-SWIZZLED kstep tiles ----
__global__ void prep_W_kernel(const float* __restrict__ W,
                              const float* __restrict__ gamma,
                              const float* __restrict__ mvar) {
    int e = blockIdx.x * 256 + threadIdx.x;
    int n = e & 511, k = e >> 9;
    float s = gamma[n] * rsqrtf(mvar[n] + BN_EPS);
    float v = W[(size_t)k * FDIM + n] * s;
    size_t byte_off = (size_t)(k >> 4) * 16384
                    + TOFF(n, (k & 15) >> 3) + (k & 7) * 2;
    *reinterpret_cast<__half*>(reinterpret_cast<char*>(g_WT) + byte_off) =
        __float2half_rn(v);
}

// ---- main fused kernel ----
__global__ __launch_bounds__(THREADS, 2)
void fused_mma_sparsemax(const float* __restrict__ x,
                         const float* __restrict__ bias,
                         const float* __restrict__ gamma,
                         const float* __restrict__ beta,
                         const float* __restrict__ mmean,
                         const float* __restrict__ mvar,
                         float* __restrict__ out)
{
    extern __shared__ char smem[];
    const uint32_t sb = smem_u32(smem);
    const int tid  = threadIdx.x;
    const int wid  = tid >> 5;             // warp col 0..7 (64 cols each)
    const int lane = tid & 31;
    const int r0   = blockIdx.x * BM;

    float acc[2][8][4];
    #pragma unroll
    for (int i = 0; i < 2; i++)
        #pragma unroll
        for (int j = 0; j < 8; j++)
            #pragma unroll
            for (int q = 0; q < 4; q++) acc[i][j][q] = 0.0f;

    // ---- A conversion role: thread -> (row, 4 consecutive k) of a 32x32 stage
    const int cv_row = tid >> 3;           // 0..31
    const int cv_k   = (tid & 7) * 4;      // 0,4,...,28
    const uint32_t cv_off = (cv_k >> 4) * 1024 +
                            TOFF(cv_row, (cv_k & 15) >> 3) + (cv_k & 7) * 2;
    const float* cv_src = x + (size_t)(r0 + cv_row) * FDIM + cv_k;

    auto cvt_sts = [&](float4 v, int s) {
        char* stg = smem + s * STAGE_BYTES;
        __half2 h01 = __floats2half2_rn(v.x, v.y);
        __half2 h23 = __floats2half2_rn(v.z, v.w);
        *reinterpret_cast<__half2*>(stg + A_O + cv_off)     = h01;
        *reinterpret_cast<__half2*>(stg + A_O + cv_off + 4) = h23;
    };

    // ---- mbarrier init (one per stage) ----
    if (tid == 0) {
        MBARRIER_INIT(sb + MBAR_O + 0,  1);
        MBARRIER_INIT(sb + MBAR_O + 8,  1);
        MBARRIER_INIT(sb + MBAR_O + 16, 1);
    }
    __syncthreads();

    // ---- B DMA: one 32KB bulk copy per stage (pre-swizzled source) ----
    auto issue_B = [&](int t, int s) {      // t = stage index (32 k each)
        MBARRIER_EXPECT_TX(sb + MBAR_O + s * 8, 32768);
        BULK_G2S(sb + s * STAGE_BYTES + B_O,
                 (const char*)g_WT + (size_t)t * 32768,
                 32768, sb + MBAR_O + s * 8);
    };

    // ldmatrix lane addressing
    const int lrow = (lane & 7) + ((lane >> 3) & 1) * 8;
    const int lkc  = (lane >> 4) & 1;
    const uint32_t t_base = TOFF(lrow, lkc);

    // ---- prologue
    float4 a_cur;
    {
        if (tid == 0) { issue_B(0, 0); issue_B(1, 1); }
        float4 a0 = *reinterpret_cast<const float4*>(cv_src);          // stage 0
        cvt_sts(a0, 0);
        a_cur = *reinterpret_cast<const float4*>(cv_src + 32);         // stage 1
    }

    int ph0 = 0, ph1 = 0, ph2 = 0;
    for (int t = 0; t < NSTAGE_IT; t++) {
        const int s = t % 3;
        if (s == 0)      { MBARRIER_WAIT_PARITY(sb + MBAR_O + 0,  ph0); ph0 ^= 1; }
        else if (s == 1) { MBARRIER_WAIT_PARITY(sb + MBAR_O + 8,  ph1); ph1 ^= 1; }
        else             { MBARRIER_WAIT_PARITY(sb + MBAR_O + 16, ph2); ph2 ^= 1; }
        __syncthreads();   // A tile of stage s visible; prior readers of the
                           // stage being overwritten below are done

        if (t + 2 < NSTAGE_IT && tid == 0) issue_B(t + 2, (t + 2) % 3);
        if (t + 1 < NSTAGE_IT) cvt_sts(a_cur, (t + 1) % 3);
        if (t + 2 < NSTAGE_IT)
            a_cur = *reinterpret_cast<const float4*>(cv_src + (t + 2) * 32);

        const uint32_t stg = sb + s * STAGE_BYTES;
        #pragma unroll
        for (int ks = 0; ks < 2; ks++) {
            const uint32_t a_b = stg + A_O + ks * 1024 + t_base;
            const uint32_t b_b = stg + B_O + ks * 16384 + t_base + wid * 2048;

            uint32_t aH[2][4];
            #pragma unroll
            for (int mt = 0; mt < 2; mt++)
                LDSM4(aH[mt], a_b + mt * 512);
            #pragma unroll
            for (int ntp = 0; ntp < 4; ntp++) {
                uint32_t bb[4];
                LDSM4(bb, b_b + ntp * 512);
                #pragma unroll
                for (int mt = 0; mt < 2; mt++) {
                    MMA16816(acc[mt][2 * ntp],     aH[mt], bb[0], bb[2]);
                    MMA16816(acc[mt][2 * ntp + 1], aH[mt], bb[1], bb[3]);
                }
            }
        }
    }
    __syncthreads();

    // ---- stage accumulators to SMEM (unions over GEMM stage buffers)
    float* stage = reinterpret_cast<float*>(smem);
    #pragma unroll
    for (int mt = 0; mt < 2; mt++) {
        #pragma unroll
        for (int nt = 0; nt < 8; nt++) {
            int row = mt * 16 + (lane >> 2);
            int col = wid * 64 + nt * 8 + (lane & 3) * 2;
            *reinterpret_cast<float2*>(&stage[row * STG_STRIDE + col]) =
                make_float2(acc[mt][nt][0], acc[mt][nt][1]);
            *reinterpret_cast<float2*>(&stage[(row + 8) * STG_STRIDE + col]) =
                make_float2(acc[mt][nt][2], acc[mt][nt][3]);
        }
    }
    __syncthreads();

    // ---- epilogue: BN shift + Michelot sparsemax, 4 rows/warp, 16 cols/lane
    float shf[16];
    #pragma unroll
    for (int j = 0; j < 16; j++) {
        int f = lane + 32 * j;
        float s = gamma[f] * rsqrtf(mvar[f] + BN_EPS);
        shf[j] = fmaf(bias[f] - mmean[f], s, beta[f]);
    }

    #pragma unroll 1
    for (int i = 0; i < 4; i++) {
        const int row = wid * 4 + i;
        float z[16];
        #pragma unroll
        for (int j = 0; j < 16; j++)
            z[j] = stage[row * STG_STRIDE + lane + 32 * j] + shf[j];

        float m = -1e30f;
        #pragma unroll
        for (int j = 0; j < 16; j++) m = fmaxf(m, z[j]);
        #pragma unroll
        for (int off = 16; off > 0; off >>= 1)
            m = fmaxf(m, __shfl_xor_sync(0xFFFFFFFFu, m, off));

        // Michelot fixed point: tau <- (sum_{z>tau} z - 1)/#{z>tau}
        float tau = m - 1.0f;
        #pragma unroll 1
        for (int it = 0; it < 24; it++) {
            float S = 0.0f, K = 0.0f;
            #pragma unroll
            for (int j = 0; j < 16; j++) {
                if (z[j] > tau) { S += z[j]; K += 1.0f; }
            }
            #pragma unroll
            for (int off = 16; off > 0; off >>= 1) {
                S += __shfl_xor_sync(0xFFFFFFFFu, S, off);
                K += __shfl_xor_sync(0xFFFFFFFFu, K, off);
            }
            float nt = (S - 1.0f) / K;
            bool done = !(nt > tau + 1e-7f);  // warp-uniform
            tau = nt;
            if (done) break;
        }

        float* orow = out + (size_t)(r0 + row) * FDIM;
        #pragma unroll
        for (int j = 0; j < 16; j++)
            orow[lane + 32 * j] = fmaxf(z[j] - tau, 0.0f);
    }
}

extern "C" void kernel_launch(void* const* d_in, const int* in_sizes, int n_in,
                              void* d_out, int out_size)
{
    const float* x     = (const float*)d_in[0];
    const float* W     = (const float*)d_in[1];
    const float* b     = (const float*)d_in[2];
    const float* gamma = (const float*)d_in[3];
    const float* beta  = (const float*)d_in[4];
    const float* mmean = (const float*)d_in[5];
    const float* mvar  = (const float*)d_in[6];
    float* out = (float*)d_out;

    cudaFuncSetAttribute(fused_mma_sparsemax,
                         cudaFuncAttributeMaxDynamicSharedMemorySize, SMEM_BYTES);

    int B = in_sizes[0] / FDIM;                       // 65536
    prep_W_kernel<<<(FDIM * FDIM) / 256, 256>>>(W, gamma, mvar);
    fused_mma_sparsemax<<<B / BM, THREADS, SMEM_BYTES>>>(x, b, gamma, beta, mmean, mvar, out);
}